// round 5
// baseline (speedup 1.0000x reference)
#include <cuda_runtime.h>
#include <cstdint>

#define NN 100000
#define EE 1600000
#define DD 128
#define SCAN_CHUNK 1024
#define SCAN_B ((NN + SCAN_CHUNK - 1) / SCAN_CHUNK)   // 98

// ---------------- static device scratch (no allocations allowed) ----------------
__device__ int   g_outdeg[NN];
__device__ int   g_indeg[NN];
__device__ float g_nsrc[NN];
__device__ float g_ndst[NN];
__device__ int   g_off[NN + 1];
__device__ int   g_cur[NN];
__device__ int   g_part[SCAN_B + 1];
__device__ int   g_esrc[EE];
__device__ float g_ew[EE];
__device__ float g_agg[(size_t)NN * DD];
__device__ float g_h1[(size_t)NN * DD];

// ---------------- setup kernels ----------------
__global__ void zero_deg_kernel(int n) {
    int i = blockIdx.x * blockDim.x + threadIdx.x;
    if (i < n) { g_outdeg[i] = 0; g_indeg[i] = 0; }
}

__global__ void count_deg_kernel(const int* __restrict__ src,
                                 const int* __restrict__ dst, int E, int n) {
    int e = blockIdx.x * blockDim.x + threadIdx.x;
    if (e < E) {
        int s = src[e];
        int d = dst[e];
        if ((unsigned)s < (unsigned)n) atomicAdd(&g_outdeg[s], 1);
        if ((unsigned)d < (unsigned)n) atomicAdd(&g_indeg[d], 1);
    }
}

__global__ void norm_kernel(int n) {
    int i = blockIdx.x * blockDim.x + threadIdx.x;
    if (i < n) {
        g_nsrc[i] = rsqrtf(fmaxf((float)g_outdeg[i], 1.0f));
        g_ndst[i] = rsqrtf(fmaxf((float)g_indeg[i], 1.0f));
    }
}

// ---- 3-pass grid scan of g_indeg -> g_off (exclusive), fused cursor init ----
__global__ __launch_bounds__(256)
void scan_reduce_kernel(int n) {
    __shared__ int wsum[8];
    int b = blockIdx.x;
    int tid = threadIdx.x;
    int idx = b * SCAN_CHUNK + tid * 4;
    int s = 0;
    #pragma unroll
    for (int t = 0; t < 4; t++)
        if (idx + t < n) s += g_indeg[idx + t];
    #pragma unroll
    for (int o = 16; o > 0; o >>= 1) s += __shfl_down_sync(0xffffffffu, s, o);
    int lane = tid & 31, wid = tid >> 5;
    if (lane == 0) wsum[wid] = s;
    __syncthreads();
    if (tid == 0) {
        int t = 0;
        #pragma unroll
        for (int w = 0; w < 8; w++) t += wsum[w];
        g_part[b] = t;
    }
}

__global__ __launch_bounds__(128)
void scan_partials_kernel(int B, int E) {
    __shared__ int sdata[128];
    int tid = threadIdx.x;
    int v = (tid < B) ? g_part[tid] : 0;
    sdata[tid] = v;
    __syncthreads();
    #pragma unroll
    for (int o = 1; o < 128; o <<= 1) {
        int t = (tid >= o) ? sdata[tid - o] : 0;
        __syncthreads();
        sdata[tid] += t;
        __syncthreads();
    }
    if (tid < B) g_part[tid] = sdata[tid] - v;
    if (tid == 0) g_off[NN] = E;
}

__global__ __launch_bounds__(256)
void scan_down_kernel(int n) {
    __shared__ int wscan[8];
    int b = blockIdx.x;
    int tid = threadIdx.x;
    int lane = tid & 31, wid = tid >> 5;
    int idx = b * SCAN_CHUNK + tid * 4;
    int v0 = 0, v1 = 0, v2 = 0, v3 = 0;
    if (idx + 0 < n) v0 = g_indeg[idx + 0];
    if (idx + 1 < n) v1 = g_indeg[idx + 1];
    if (idx + 2 < n) v2 = g_indeg[idx + 2];
    if (idx + 3 < n) v3 = g_indeg[idx + 3];
    int tsum = v0 + v1 + v2 + v3;
    int x = tsum;
    #pragma unroll
    for (int o = 1; o < 32; o <<= 1) {
        int y = __shfl_up_sync(0xffffffffu, x, o);
        if (lane >= o) x += y;
    }
    if (lane == 31) wscan[wid] = x;
    __syncthreads();
    if (wid == 0 && lane < 8) {
        int s = wscan[lane];
        #pragma unroll
        for (int o = 1; o < 8; o <<= 1) {
            int y = __shfl_up_sync(0x000000ffu, s, o);
            if (lane >= o) s += y;
        }
        wscan[lane] = s;
    }
    __syncthreads();
    int base = g_part[b] + (wid ? wscan[wid - 1] : 0) + (x - tsum);
    if (idx + 0 < n) { g_off[idx + 0] = base;            g_cur[idx + 0] = base; }
    if (idx + 1 < n) { g_off[idx + 1] = base + v0;       g_cur[idx + 1] = base + v0; }
    if (idx + 2 < n) { int t = base + v0 + v1;      g_off[idx + 2] = t; g_cur[idx + 2] = t; }
    if (idx + 3 < n) { int t = base + v0 + v1 + v2; g_off[idx + 3] = t; g_cur[idx + 3] = t; }
}

__global__ void fill_csr_kernel(const int* __restrict__ src,
                                const int* __restrict__ dst, int E, int n) {
    int e = blockIdx.x * blockDim.x + threadIdx.x;
    if (e < E) {
        int s = src[e];
        int d = dst[e];
        if ((unsigned)s < (unsigned)n && (unsigned)d < (unsigned)n) {
            int pos = atomicAdd(&g_cur[d], 1);
            g_esrc[pos] = s;
            g_ew[pos] = g_nsrc[s];
        }
    }
}

// ---------------- pull-based SpMM: one warp per dst node ----------------
__global__ __launch_bounds__(256)
void spmm_kernel(const float* __restrict__ h, float* __restrict__ agg, int n) {
    int gw = (blockIdx.x * blockDim.x + threadIdx.x) >> 5;
    if (gw >= n) return;
    int lane = threadIdx.x & 31;
    int beg = g_off[gw];
    int end = g_off[gw + 1];
    const float4* hp = (const float4*)h;
    float4 acc = make_float4(0.f, 0.f, 0.f, 0.f);
    int e = beg;
    for (; e + 1 < end; e += 2) {
        int u0 = g_esrc[e];
        int u1 = g_esrc[e + 1];
        float s0 = g_ew[e];
        float s1 = g_ew[e + 1];
        float4 v0 = hp[(size_t)u0 * 32 + lane];
        float4 v1 = hp[(size_t)u1 * 32 + lane];
        acc.x += s0 * v0.x + s1 * v1.x;
        acc.y += s0 * v0.y + s1 * v1.y;
        acc.z += s0 * v0.z + s1 * v1.z;
        acc.w += s0 * v0.w + s1 * v1.w;
    }
    if (e < end) {
        int u0 = g_esrc[e];
        float s0 = g_ew[e];
        float4 v0 = hp[(size_t)u0 * 32 + lane];
        acc.x += s0 * v0.x;
        acc.y += s0 * v0.y;
        acc.z += s0 * v0.z;
        acc.w += s0 * v0.w;
    }
    float nd = g_ndst[gw];
    float4 o = make_float4(acc.x * nd, acc.y * nd, acc.z * nd, acc.w * nd);
    ((float4*)agg)[(size_t)gw * 32 + lane] = o;
}

// ---------------- fp32 GEMM + bias + relu via packed f32x2 FMA ----------------
// C[N,128] = relu(A[N,128] @ W[128,128] + b)
// FFMA2: one issue slot = 2 fp32 FMAs (pattern ptxas never emits from C++).
__global__ __launch_bounds__(256, 2)
void gemm_bias_relu_kernel(const float* __restrict__ A, const float* __restrict__ W,
                           const float* __restrict__ bias, float* __restrict__ C, int n) {
    __shared__ float As[16][132];   // padded to kill bank conflicts on transpose-store
    __shared__ float Ws[16][128];
    int tid = threadIdx.x;
    int row0 = blockIdx.x * 128;
    int tx = tid & 15;      // col group: cols tx*8 .. tx*8+7
    int ty = tid >> 4;      // row group: rows ty*8 .. ty*8+7

    // packed accumulators: 8 rows x 4 col-pairs
    unsigned long long acc[8][4];
    #pragma unroll
    for (int i = 0; i < 8; i++)
        #pragma unroll
        for (int j = 0; j < 4; j++) acc[i][j] = 0ULL;

    for (int k0 = 0; k0 < DD; k0 += 16) {
        #pragma unroll
        for (int t = 0; t < 2; t++) {
            int f4 = tid * 2 + t;       // 0..511
            int m  = f4 >> 2;           // 0..127
            int kq = f4 & 3;            // 0..3
            float4 v = make_float4(0.f, 0.f, 0.f, 0.f);
            int r = row0 + m;
            if (r < n) v = *(const float4*)(A + (size_t)r * DD + k0 + kq * 4);
            As[kq * 4 + 0][m] = v.x;
            As[kq * 4 + 1][m] = v.y;
            As[kq * 4 + 2][m] = v.z;
            As[kq * 4 + 3][m] = v.w;
        }
        #pragma unroll
        for (int t = 0; t < 2; t++) {
            int f4 = tid * 2 + t;       // 0..511
            int kk = f4 >> 5;           // 0..15
            int nq = f4 & 31;           // 0..31
            float4 v = *(const float4*)(W + (size_t)(k0 + kk) * DD + nq * 4);
            *(float4*)&Ws[kk][nq * 4] = v;
        }
        __syncthreads();
        #pragma unroll
        for (int kk = 0; kk < 16; kk++) {
            // broadcast-packed a values: {a, a}
            unsigned long long ad[8];
            #pragma unroll
            for (int i = 0; i < 8; i++) {
                float a = As[kk][ty * 8 + i];
                asm("mov.b64 %0, {%1, %1};" : "=l"(ad[i]) : "f"(a));
            }
            // packed w pairs (8-byte aligned: tx*8 is even)
            unsigned long long wp[4];
            #pragma unroll
            for (int j = 0; j < 4; j++)
                wp[j] = *(const unsigned long long*)&Ws[kk][tx * 8 + 2 * j];
            #pragma unroll
            for (int i = 0; i < 8; i++)
                #pragma unroll
                for (int j = 0; j < 4; j++)
                    asm("fma.rn.f32x2 %0, %1, %2, %0;"
                        : "+l"(acc[i][j]) : "l"(ad[i]), "l"(wp[j]));
        }
        __syncthreads();
    }

    float bv[8];
    #pragma unroll
    for (int j = 0; j < 8; j++) bv[j] = bias[tx * 8 + j];
    #pragma unroll
    for (int i = 0; i < 8; i++) {
        int r = row0 + ty * 8 + i;
        if (r < n) {
            float c[8];
            #pragma unroll
            for (int j = 0; j < 4; j++) {
                float lo, hi;
                asm("mov.b64 {%0, %1}, %2;" : "=f"(lo), "=f"(hi) : "l"(acc[i][j]));
                c[2 * j] = lo;
                c[2 * j + 1] = hi;
            }
            float4 o0, o1;
            o0.x = fmaxf(c[0] + bv[0], 0.f);
            o0.y = fmaxf(c[1] + bv[1], 0.f);
            o0.z = fmaxf(c[2] + bv[2], 0.f);
            o0.w = fmaxf(c[3] + bv[3], 0.f);
            o1.x = fmaxf(c[4] + bv[4], 0.f);
            o1.y = fmaxf(c[5] + bv[5], 0.f);
            o1.z = fmaxf(c[6] + bv[6], 0.f);
            o1.w = fmaxf(c[7] + bv[7], 0.f);
            *(float4*)(C + (size_t)r * DD + tx * 8)     = o0;
            *(float4*)(C + (size_t)r * DD + tx * 8 + 4) = o1;
        }
    }
}

// ---------------- launch ----------------
extern "C" void kernel_launch(void* const* d_in, const int* in_sizes, int n_in,
                              void* d_out, int out_size) {
    const float* features = (const float*)d_in[0];
    const int*   src      = (const int*)d_in[1];   // jnp.int64 downgrades to int32 (x64 off)
    const int*   dst      = (const int*)d_in[2];
    const float* W1       = (const float*)d_in[3];
    const float* b1       = (const float*)d_in[4];
    const float* W2       = (const float*)d_in[5];
    const float* b2       = (const float*)d_in[6];
    float*       out      = (float*)d_out;

    int n = in_sizes[0] / DD;   // 100000
    int E = in_sizes[1];        // 1600000

    float *agg, *h1;
    cudaGetSymbolAddress((void**)&agg, g_agg);
    cudaGetSymbolAddress((void**)&h1, g_h1);

    int tb = 256;
    int gN = (n + tb - 1) / tb;
    int gE = (E + tb - 1) / tb;
    int gSp = ((n * 32) + tb - 1) / tb;
    int gGemm = (n + 127) / 128;
    int B = (n + SCAN_CHUNK - 1) / SCAN_CHUNK;

    zero_deg_kernel<<<gN, tb>>>(n);
    count_deg_kernel<<<gE, tb>>>(src, dst, E, n);
    norm_kernel<<<gN, tb>>>(n);
    scan_reduce_kernel<<<B, 256>>>(n);
    scan_partials_kernel<<<1, 128>>>(B, E);
    scan_down_kernel<<<B, 256>>>(n);
    fill_csr_kernel<<<gE, tb>>>(src, dst, E, n);

    // layer 1
    spmm_kernel<<<gSp, tb>>>(features, agg, n);
    gemm_bias_relu_kernel<<<gGemm, tb>>>(agg, W1, b1, h1, n);
    // layer 2
    spmm_kernel<<<gSp, tb>>>(h1, agg, n);
    gemm_bias_relu_kernel<<<gGemm, tb>>>(agg, W2, b2, out, n);
}

// round 6
// speedup vs baseline: 1.1919x; 1.1919x over previous
#include <cuda_runtime.h>
#include <cuda_bf16.h>
#include <cstdint>

#define NN 100000
#define EE 1600000
#define DD 128
#define SCAN_CHUNK 1024
#define SCAN_B ((NN + SCAN_CHUNK - 1) / SCAN_CHUNK)   // 98

// ---------------- static device scratch (no allocations allowed) ----------------
__device__ int   g_outdeg[NN];
__device__ int   g_indeg[NN];
__device__ float g_nsrc[NN];
__device__ float g_ndst[NN];
__device__ int   g_off[NN + 1];
__device__ int   g_cur[NN];
__device__ int   g_part[SCAN_B + 1];
__device__ int   g_esrc[EE];
__device__ float g_ew[EE];
__device__ float g_G[(size_t)NN * DD];    // GEMM output (pre-aggregation)
__device__ float g_h1[(size_t)NN * DD];
__device__ __nv_bfloat16 g_Whi1[DD * DD];
__device__ __nv_bfloat16 g_Wlo1[DD * DD];
__device__ __nv_bfloat16 g_Whi2[DD * DD];
__device__ __nv_bfloat16 g_Wlo2[DD * DD];

__device__ __forceinline__ uint32_t smem_u32(const void* p) {
    uint32_t a;
    asm("{ .reg .u64 t; cvta.to.shared.u64 t, %1; cvt.u32.u64 %0, t; }" : "=r"(a) : "l"(p));
    return a;
}

// ---------------- setup kernels ----------------
__global__ void zero_deg_kernel(int n) {
    int i = blockIdx.x * blockDim.x + threadIdx.x;
    if (i < n) { g_outdeg[i] = 0; g_indeg[i] = 0; }
}

__global__ void count_deg_kernel(const int* __restrict__ src,
                                 const int* __restrict__ dst, int E, int n) {
    int e = blockIdx.x * blockDim.x + threadIdx.x;
    if (e < E) {
        int s = src[e];
        int d = dst[e];
        if ((unsigned)s < (unsigned)n) atomicAdd(&g_outdeg[s], 1);
        if ((unsigned)d < (unsigned)n) atomicAdd(&g_indeg[d], 1);
    }
}

__global__ void norm_kernel(int n) {
    int i = blockIdx.x * blockDim.x + threadIdx.x;
    if (i < n) {
        g_nsrc[i] = rsqrtf(fmaxf((float)g_outdeg[i], 1.0f));
        g_ndst[i] = rsqrtf(fmaxf((float)g_indeg[i], 1.0f));
    }
}

// W [K,N] fp32 row-major -> transposed bf16 hi/lo [N,K]
__global__ void wconv_kernel(const float* __restrict__ W,
                             __nv_bfloat16* __restrict__ hi, __nv_bfloat16* __restrict__ lo) {
    int idx = blockIdx.x * blockDim.x + threadIdx.x;
    if (idx < DD * DD) {
        int k = idx >> 7, nn = idx & 127;
        float w = W[idx];
        __nv_bfloat16 h = __float2bfloat16_rn(w);
        float r = w - __bfloat162float(h);
        hi[nn * DD + k] = h;
        lo[nn * DD + k] = __float2bfloat16_rn(r);
    }
}

// ---- 3-pass grid scan of g_indeg -> g_off (exclusive), fused cursor init ----
__global__ __launch_bounds__(256)
void scan_reduce_kernel(int n) {
    __shared__ int wsum[8];
    int b = blockIdx.x;
    int tid = threadIdx.x;
    int idx = b * SCAN_CHUNK + tid * 4;
    int s = 0;
    #pragma unroll
    for (int t = 0; t < 4; t++)
        if (idx + t < n) s += g_indeg[idx + t];
    #pragma unroll
    for (int o = 16; o > 0; o >>= 1) s += __shfl_down_sync(0xffffffffu, s, o);
    int lane = tid & 31, wid = tid >> 5;
    if (lane == 0) wsum[wid] = s;
    __syncthreads();
    if (tid == 0) {
        int t = 0;
        #pragma unroll
        for (int w = 0; w < 8; w++) t += wsum[w];
        g_part[b] = t;
    }
}

__global__ __launch_bounds__(128)
void scan_partials_kernel(int B, int E) {
    __shared__ int sdata[128];
    int tid = threadIdx.x;
    int v = (tid < B) ? g_part[tid] : 0;
    sdata[tid] = v;
    __syncthreads();
    #pragma unroll
    for (int o = 1; o < 128; o <<= 1) {
        int t = (tid >= o) ? sdata[tid - o] : 0;
        __syncthreads();
        sdata[tid] += t;
        __syncthreads();
    }
    if (tid < B) g_part[tid] = sdata[tid] - v;
    if (tid == 0) g_off[NN] = E;
}

__global__ __launch_bounds__(256)
void scan_down_kernel(int n) {
    __shared__ int wscan[8];
    int b = blockIdx.x;
    int tid = threadIdx.x;
    int lane = tid & 31, wid = tid >> 5;
    int idx = b * SCAN_CHUNK + tid * 4;
    int v0 = 0, v1 = 0, v2 = 0, v3 = 0;
    if (idx + 0 < n) v0 = g_indeg[idx + 0];
    if (idx + 1 < n) v1 = g_indeg[idx + 1];
    if (idx + 2 < n) v2 = g_indeg[idx + 2];
    if (idx + 3 < n) v3 = g_indeg[idx + 3];
    int tsum = v0 + v1 + v2 + v3;
    int x = tsum;
    #pragma unroll
    for (int o = 1; o < 32; o <<= 1) {
        int y = __shfl_up_sync(0xffffffffu, x, o);
        if (lane >= o) x += y;
    }
    if (lane == 31) wscan[wid] = x;
    __syncthreads();
    if (wid == 0 && lane < 8) {
        int s = wscan[lane];
        #pragma unroll
        for (int o = 1; o < 8; o <<= 1) {
            int y = __shfl_up_sync(0x000000ffu, s, o);
            if (lane >= o) s += y;
        }
        wscan[lane] = s;
    }
    __syncthreads();
    int base = g_part[b] + (wid ? wscan[wid - 1] : 0) + (x - tsum);
    if (idx + 0 < n) { g_off[idx + 0] = base;            g_cur[idx + 0] = base; }
    if (idx + 1 < n) { g_off[idx + 1] = base + v0;       g_cur[idx + 1] = base + v0; }
    if (idx + 2 < n) { int t = base + v0 + v1;      g_off[idx + 2] = t; g_cur[idx + 2] = t; }
    if (idx + 3 < n) { int t = base + v0 + v1 + v2; g_off[idx + 3] = t; g_cur[idx + 3] = t; }
}

__global__ void fill_csr_kernel(const int* __restrict__ src,
                                const int* __restrict__ dst, int E, int n) {
    int e = blockIdx.x * blockDim.x + threadIdx.x;
    if (e < E) {
        int s = src[e];
        int d = dst[e];
        if ((unsigned)s < (unsigned)n && (unsigned)d < (unsigned)n) {
            int pos = atomicAdd(&g_cur[d], 1);
            g_esrc[pos] = s;
            g_ew[pos] = g_nsrc[s];
        }
    }
}

// ---------------- pull-based SpMM + fused nd/bias/relu epilogue ----------------
// out[d] = relu(nd[d] * sum_e ns[src_e]*G[src_e] + bias)
__global__ __launch_bounds__(256)
void spmm_kernel(const float* __restrict__ G, const float* __restrict__ bias,
                 float* __restrict__ out, int n) {
    int gw = (blockIdx.x * blockDim.x + threadIdx.x) >> 5;
    if (gw >= n) return;
    int lane = threadIdx.x & 31;
    int beg = g_off[gw];
    int end = g_off[gw + 1];
    const float4* hp = (const float4*)G;
    float4 acc = make_float4(0.f, 0.f, 0.f, 0.f);
    int e = beg;
    for (; e + 1 < end; e += 2) {
        int u0 = g_esrc[e];
        int u1 = g_esrc[e + 1];
        float s0 = g_ew[e];
        float s1 = g_ew[e + 1];
        float4 v0 = hp[(size_t)u0 * 32 + lane];
        float4 v1 = hp[(size_t)u1 * 32 + lane];
        acc.x += s0 * v0.x + s1 * v1.x;
        acc.y += s0 * v0.y + s1 * v1.y;
        acc.z += s0 * v0.z + s1 * v1.z;
        acc.w += s0 * v0.w + s1 * v1.w;
    }
    if (e < end) {
        int u0 = g_esrc[e];
        float s0 = g_ew[e];
        float4 v0 = hp[(size_t)u0 * 32 + lane];
        acc.x += s0 * v0.x;
        acc.y += s0 * v0.y;
        acc.z += s0 * v0.z;
        acc.w += s0 * v0.w;
    }
    float nd = g_ndst[gw];
    float4 b4 = ((const float4*)bias)[lane];
    float4 o;
    o.x = fmaxf(acc.x * nd + b4.x, 0.f);
    o.y = fmaxf(acc.y * nd + b4.y, 0.f);
    o.z = fmaxf(acc.z * nd + b4.z, 0.f);
    o.w = fmaxf(acc.w * nd + b4.w, 0.f);
    ((float4*)out)[(size_t)gw * 32 + lane] = o;
}

// ---------------- HMMA (mma.sync bf16) pure GEMM: C = A @ W ----------------
// A fp32 [n,128] split on the fly to bf16 hi/lo; W pre-split [N=128,K=128] bf16.
// 3 passes: Ahi*Whi + Ahi*Wlo + Alo*Whi, fp32 accumulation.
#define GP 272                       // smem row pitch bytes (17*16: ldmatrix conflict-free)
#define SM_AHI 0
#define SM_ALO (128 * GP)
#define SM_WHI (2 * 128 * GP)
#define SM_WLO (3 * 128 * GP)
#define GEMM_SMEM (4 * 128 * GP)     // 139264 B

__device__ __forceinline__ void ldsm_x4(uint32_t* r, uint32_t addr) {
    asm volatile("ldmatrix.sync.aligned.m8n8.x4.shared.b16 {%0,%1,%2,%3}, [%4];"
                 : "=r"(r[0]), "=r"(r[1]), "=r"(r[2]), "=r"(r[3]) : "r"(addr));
}
__device__ __forceinline__ void ldsm_x2(uint32_t& r0, uint32_t& r1, uint32_t addr) {
    asm volatile("ldmatrix.sync.aligned.m8n8.x2.shared.b16 {%0,%1}, [%2];"
                 : "=r"(r0), "=r"(r1) : "r"(addr));
}
__device__ __forceinline__ void mma_bf16(float* c, const uint32_t* a, uint32_t b0, uint32_t b1) {
    asm volatile("mma.sync.aligned.m16n8k16.row.col.f32.bf16.bf16.f32 "
                 "{%0,%1,%2,%3}, {%4,%5,%6,%7}, {%8,%9}, {%0,%1,%2,%3};"
                 : "+f"(c[0]), "+f"(c[1]), "+f"(c[2]), "+f"(c[3])
                 : "r"(a[0]), "r"(a[1]), "r"(a[2]), "r"(a[3]), "r"(b0), "r"(b1));
}

__device__ __forceinline__ uint32_t pack_bf16(float a, float b) {
    __nv_bfloat16 ah = __float2bfloat16_rn(a);
    __nv_bfloat16 bh = __float2bfloat16_rn(b);
    return (uint32_t)__bfloat16_as_ushort(ah) | ((uint32_t)__bfloat16_as_ushort(bh) << 16);
}

__global__ __launch_bounds__(256, 1)
void gemm_tc_kernel(const float* __restrict__ A,
                    const __nv_bfloat16* __restrict__ Whi,
                    const __nv_bfloat16* __restrict__ Wlo,
                    float* __restrict__ C, int n) {
    extern __shared__ char sm[];
    uint32_t base = smem_u32(sm);
    const int tid = threadIdx.x;
    const int w = tid >> 5, lane = tid & 31;
    const int row0 = blockIdx.x * 128;

    // W tiles: 128 rows x 256B (16 uint4) each, into pitch-GP smem
    for (int i = tid; i < 2048; i += 256) {
        int rr = i >> 4, q = i & 15;
        *(uint4*)(sm + SM_WHI + rr * GP + q * 16) = ((const uint4*)Whi)[rr * 16 + q];
        *(uint4*)(sm + SM_WLO + rr * GP + q * 16) = ((const uint4*)Wlo)[rr * 16 + q];
    }
    // A tile: split fp32 -> bf16 hi/lo (2 threads per row, 64 cols each)
    {
        int r = tid >> 1, half = tid & 1;
        int gr = row0 + r;
        const float4* ap = (const float4*)(A + (size_t)gr * DD + half * 64);
        #pragma unroll
        for (int i = 0; i < 16; i++) {
            float4 v = make_float4(0.f, 0.f, 0.f, 0.f);
            if (gr < n) v = ap[i];
            __nv_bfloat16 hx = __float2bfloat16_rn(v.x), hy = __float2bfloat16_rn(v.y);
            __nv_bfloat16 hz = __float2bfloat16_rn(v.z), hw = __float2bfloat16_rn(v.w);
            uint32_t hi01 = (uint32_t)__bfloat16_as_ushort(hx) | ((uint32_t)__bfloat16_as_ushort(hy) << 16);
            uint32_t hi23 = (uint32_t)__bfloat16_as_ushort(hz) | ((uint32_t)__bfloat16_as_ushort(hw) << 16);
            uint32_t lo01 = pack_bf16(v.x - __bfloat162float(hx), v.y - __bfloat162float(hy));
            uint32_t lo23 = pack_bf16(v.z - __bfloat162float(hz), v.w - __bfloat162float(hw));
            int koff = (half * 64 + i * 4) * 2;   // byte offset in row
            *(uint2*)(sm + SM_AHI + r * GP + koff) = make_uint2(hi01, hi23);
            *(uint2*)(sm + SM_ALO + r * GP + koff) = make_uint2(lo01, lo23);
        }
    }
    __syncthreads();

    float acc[16][4];
    #pragma unroll
    for (int j = 0; j < 16; j++)
        #pragma unroll
        for (int q = 0; q < 4; q++) acc[j][q] = 0.f;

    // ldmatrix lane addresses
    int i4 = lane >> 3, l7 = lane & 7;
    uint32_t aRow = (uint32_t)(w * 16 + (i4 & 1) * 8 + l7);
    uint32_t aK8  = (uint32_t)((i4 >> 1) * 8);
    uint32_t aHi = base + SM_AHI + aRow * GP + aK8 * 2;
    uint32_t aLo = base + SM_ALO + aRow * GP + aK8 * 2;
    uint32_t wRow = (uint32_t)(lane & 7);
    uint32_t wK8  = (uint32_t)(((lane >> 3) & 1) * 8);
    uint32_t wHi = base + SM_WHI + wRow * GP + wK8 * 2;
    uint32_t wLo = base + SM_WLO + wRow * GP + wK8 * 2;

    #pragma unroll
    for (int kk = 0; kk < 8; kk++) {
        uint32_t ah[4], al[4];
        ldsm_x4(ah, aHi + kk * 32);
        ldsm_x4(al, aLo + kk * 32);
        #pragma unroll
        for (int j = 0; j < 16; j++) {
            uint32_t bh0, bh1, bl0, bl1;
            ldsm_x2(bh0, bh1, wHi + j * 8 * GP + kk * 32);
            ldsm_x2(bl0, bl1, wLo + j * 8 * GP + kk * 32);
            mma_bf16(acc[j], ah, bh0, bh1);
            mma_bf16(acc[j], ah, bl0, bl1);
            mma_bf16(acc[j], al, bh0, bh1);
        }
    }

    // epilogue: write fp32 C
    int r0 = row0 + w * 16 + (lane >> 2);
    int c0 = (lane & 3) * 2;
    #pragma unroll
    for (int j = 0; j < 16; j++) {
        int nn = j * 8 + c0;
        if (r0 < n)     *(float2*)(C + (size_t)r0 * DD + nn)       = make_float2(acc[j][0], acc[j][1]);
        if (r0 + 8 < n) *(float2*)(C + (size_t)(r0 + 8) * DD + nn) = make_float2(acc[j][2], acc[j][3]);
    }
}

// ---------------- launch ----------------
extern "C" void kernel_launch(void* const* d_in, const int* in_sizes, int n_in,
                              void* d_out, int out_size) {
    const float* features = (const float*)d_in[0];
    const int*   src      = (const int*)d_in[1];   // jnp.int64 downgrades to int32 (x64 off)
    const int*   dst      = (const int*)d_in[2];
    const float* W1       = (const float*)d_in[3];
    const float* b1       = (const float*)d_in[4];
    const float* W2       = (const float*)d_in[5];
    const float* b2       = (const float*)d_in[6];
    float*       out      = (float*)d_out;

    int n = in_sizes[0] / DD;   // 100000
    int E = in_sizes[1];        // 1600000

    float *G, *h1;
    __nv_bfloat16 *whi1, *wlo1, *whi2, *wlo2;
    cudaGetSymbolAddress((void**)&G, g_G);
    cudaGetSymbolAddress((void**)&h1, g_h1);
    cudaGetSymbolAddress((void**)&whi1, g_Whi1);
    cudaGetSymbolAddress((void**)&wlo1, g_Wlo1);
    cudaGetSymbolAddress((void**)&whi2, g_Whi2);
    cudaGetSymbolAddress((void**)&wlo2, g_Wlo2);

    cudaFuncSetAttribute(gemm_tc_kernel,
                         cudaFuncAttributeMaxDynamicSharedMemorySize, GEMM_SMEM);

    int tb = 256;
    int gN = (n + tb - 1) / tb;
    int gE = (E + tb - 1) / tb;
    int gSp = ((n * 32) + tb - 1) / tb;
    int gGemm = (n + 127) / 128;
    int B = (n + SCAN_CHUNK - 1) / SCAN_CHUNK;

    // GEMM1 = features @ W1 needs no graph info (agg/scale commute with right-matmul)
    wconv_kernel<<<64, 256>>>(W1, whi1, wlo1);
    wconv_kernel<<<64, 256>>>(W2, whi2, wlo2);
    gemm_tc_kernel<<<gGemm, 256, GEMM_SMEM>>>(features, whi1, wlo1, G, n);

    // CSR setup
    zero_deg_kernel<<<gN, tb>>>(n);
    count_deg_kernel<<<gE, tb>>>(src, dst, E, n);
    norm_kernel<<<gN, tb>>>(n);
    scan_reduce_kernel<<<B, 256>>>(n);
    scan_partials_kernel<<<1, 128>>>(B, E);
    scan_down_kernel<<<B, 256>>>(n);
    fill_csr_kernel<<<gE, tb>>>(src, dst, E, n);

    // layer 1 aggregation (+ nd, bias, relu fused)
    spmm_kernel<<<gSp, tb>>>(G, b1, h1, n);
    // layer 2
    gemm_tc_kernel<<<gGemm, 256, GEMM_SMEM>>>(h1, whi2, wlo2, G, n);
    spmm_kernel<<<gSp, tb>>>(G, b2, out, n);
}

// round 7
// speedup vs baseline: 1.4399x; 1.2081x over previous
#include <cuda_runtime.h>
#include <cuda_bf16.h>
#include <cuda_fp16.h>
#include <cstdint>

#define NN 100000
#define EE 1600000
#define DD 128
#define SCAN_CHUNK 1024
#define SCAN_B ((NN + SCAN_CHUNK - 1) / SCAN_CHUNK)   // 98

// ---------------- static device scratch (no allocations allowed) ----------------
__device__ int    g_outdeg[NN];
__device__ int    g_indeg[NN];
__device__ float  g_nsrc[NN];
__device__ float  g_ndst[NN];
__device__ int    g_off[NN + 1];
__device__ int    g_cur[NN];
__device__ int    g_part[SCAN_B + 1];
__device__ int    g_esrc[EE];
__device__ __half g_G[(size_t)NN * DD];    // ns-scaled GEMM output (gather source)
__device__ __half g_h1[(size_t)NN * DD];   // layer-1 activations
__device__ __nv_bfloat16 g_Whi1[DD * DD];
__device__ __nv_bfloat16 g_Wlo1[DD * DD];
__device__ __nv_bfloat16 g_Whi2[DD * DD];
__device__ __nv_bfloat16 g_Wlo2[DD * DD];

__device__ __forceinline__ uint32_t smem_u32(const void* p) {
    uint32_t a;
    asm("{ .reg .u64 t; cvta.to.shared.u64 t, %1; cvt.u32.u64 %0, t; }" : "=r"(a) : "l"(p));
    return a;
}

// ---------------- setup kernels ----------------
__global__ void zero_deg_kernel(int n) {
    int i = blockIdx.x * blockDim.x + threadIdx.x;
    if (i < n) { g_outdeg[i] = 0; g_indeg[i] = 0; }
}

__global__ void count_deg_kernel(const int* __restrict__ src,
                                 const int* __restrict__ dst, int E, int n) {
    int e = blockIdx.x * blockDim.x + threadIdx.x;
    if (e < E) {
        int s = src[e];
        int d = dst[e];
        if ((unsigned)s < (unsigned)n) atomicAdd(&g_outdeg[s], 1);
        if ((unsigned)d < (unsigned)n) atomicAdd(&g_indeg[d], 1);
    }
}

__global__ void norm_kernel(int n) {
    int i = blockIdx.x * blockDim.x + threadIdx.x;
    if (i < n) {
        g_nsrc[i] = rsqrtf(fmaxf((float)g_outdeg[i], 1.0f));
        g_ndst[i] = rsqrtf(fmaxf((float)g_indeg[i], 1.0f));
    }
}

// W [K,N] fp32 row-major -> transposed bf16 hi/lo [N,K]
__global__ void wconv_kernel(const float* __restrict__ W,
                             __nv_bfloat16* __restrict__ hi, __nv_bfloat16* __restrict__ lo) {
    int idx = blockIdx.x * blockDim.x + threadIdx.x;
    if (idx < DD * DD) {
        int k = idx >> 7, nn = idx & 127;
        float w = W[idx];
        __nv_bfloat16 h = __float2bfloat16_rn(w);
        float r = w - __bfloat162float(h);
        hi[nn * DD + k] = h;
        lo[nn * DD + k] = __float2bfloat16_rn(r);
    }
}

// ---- 3-pass grid scan of g_indeg -> g_off (exclusive), fused cursor init ----
__global__ __launch_bounds__(256)
void scan_reduce_kernel(int n) {
    __shared__ int wsum[8];
    int b = blockIdx.x;
    int tid = threadIdx.x;
    int idx = b * SCAN_CHUNK + tid * 4;
    int s = 0;
    #pragma unroll
    for (int t = 0; t < 4; t++)
        if (idx + t < n) s += g_indeg[idx + t];
    #pragma unroll
    for (int o = 16; o > 0; o >>= 1) s += __shfl_down_sync(0xffffffffu, s, o);
    int lane = tid & 31, wid = tid >> 5;
    if (lane == 0) wsum[wid] = s;
    __syncthreads();
    if (tid == 0) {
        int t = 0;
        #pragma unroll
        for (int w = 0; w < 8; w++) t += wsum[w];
        g_part[b] = t;
    }
}

__global__ __launch_bounds__(128)
void scan_partials_kernel(int B, int E) {
    __shared__ int sdata[128];
    int tid = threadIdx.x;
    int v = (tid < B) ? g_part[tid] : 0;
    sdata[tid] = v;
    __syncthreads();
    #pragma unroll
    for (int o = 1; o < 128; o <<= 1) {
        int t = (tid >= o) ? sdata[tid - o] : 0;
        __syncthreads();
        sdata[tid] += t;
        __syncthreads();
    }
    if (tid < B) g_part[tid] = sdata[tid] - v;
    if (tid == 0) g_off[NN] = E;
}

__global__ __launch_bounds__(256)
void scan_down_kernel(int n) {
    __shared__ int wscan[8];
    int b = blockIdx.x;
    int tid = threadIdx.x;
    int lane = tid & 31, wid = tid >> 5;
    int idx = b * SCAN_CHUNK + tid * 4;
    int v0 = 0, v1 = 0, v2 = 0, v3 = 0;
    if (idx + 0 < n) v0 = g_indeg[idx + 0];
    if (idx + 1 < n) v1 = g_indeg[idx + 1];
    if (idx + 2 < n) v2 = g_indeg[idx + 2];
    if (idx + 3 < n) v3 = g_indeg[idx + 3];
    int tsum = v0 + v1 + v2 + v3;
    int x = tsum;
    #pragma unroll
    for (int o = 1; o < 32; o <<= 1) {
        int y = __shfl_up_sync(0xffffffffu, x, o);
        if (lane >= o) x += y;
    }
    if (lane == 31) wscan[wid] = x;
    __syncthreads();
    if (wid == 0 && lane < 8) {
        int s = wscan[lane];
        #pragma unroll
        for (int o = 1; o < 8; o <<= 1) {
            int y = __shfl_up_sync(0x000000ffu, s, o);
            if (lane >= o) s += y;
        }
        wscan[lane] = s;
    }
    __syncthreads();
    int base = g_part[b] + (wid ? wscan[wid - 1] : 0) + (x - tsum);
    if (idx + 0 < n) { g_off[idx + 0] = base;            g_cur[idx + 0] = base; }
    if (idx + 1 < n) { g_off[idx + 1] = base + v0;       g_cur[idx + 1] = base + v0; }
    if (idx + 2 < n) { int t = base + v0 + v1;      g_off[idx + 2] = t; g_cur[idx + 2] = t; }
    if (idx + 3 < n) { int t = base + v0 + v1 + v2; g_off[idx + 3] = t; g_cur[idx + 3] = t; }
}

__global__ void fill_csr_kernel(const int* __restrict__ src,
                                const int* __restrict__ dst, int E, int n) {
    int e = blockIdx.x * blockDim.x + threadIdx.x;
    if (e < E) {
        int s = src[e];
        int d = dst[e];
        if ((unsigned)s < (unsigned)n && (unsigned)d < (unsigned)n) {
            int pos = atomicAdd(&g_cur[d], 1);
            g_esrc[pos] = s;
        }
    }
}

// ---------------- pull-based SpMM (fp16 gather) + fused nd/bias/relu ----------------
// out[d] = relu(nd[d] * sum_e G[src_e] + bias)   (ns already folded into G)
template <typename TOut>
__global__ __launch_bounds__(256)
void spmm_kernel(const __half* __restrict__ G, const float* __restrict__ bias,
                 TOut* __restrict__ out, int n) {
    int gw = (blockIdx.x * blockDim.x + threadIdx.x) >> 5;
    if (gw >= n) return;
    int lane = threadIdx.x & 31;
    int beg = g_off[gw];
    int end = g_off[gw + 1];
    const uint2* hp = (const uint2*)G;   // 4 halfs per lane, 32 lanes = 128-col row
    float4 acc = make_float4(0.f, 0.f, 0.f, 0.f);
    int e = beg;
    for (; e + 3 < end; e += 4) {
        int u0 = g_esrc[e], u1 = g_esrc[e + 1], u2 = g_esrc[e + 2], u3 = g_esrc[e + 3];
        uint2 a = hp[(size_t)u0 * 32 + lane];
        uint2 b = hp[(size_t)u1 * 32 + lane];
        uint2 c = hp[(size_t)u2 * 32 + lane];
        uint2 d = hp[(size_t)u3 * 32 + lane];
        float2 f;
        f = __half22float2(*(__half2*)&a.x); acc.x += f.x; acc.y += f.y;
        f = __half22float2(*(__half2*)&a.y); acc.z += f.x; acc.w += f.y;
        f = __half22float2(*(__half2*)&b.x); acc.x += f.x; acc.y += f.y;
        f = __half22float2(*(__half2*)&b.y); acc.z += f.x; acc.w += f.y;
        f = __half22float2(*(__half2*)&c.x); acc.x += f.x; acc.y += f.y;
        f = __half22float2(*(__half2*)&c.y); acc.z += f.x; acc.w += f.y;
        f = __half22float2(*(__half2*)&d.x); acc.x += f.x; acc.y += f.y;
        f = __half22float2(*(__half2*)&d.y); acc.z += f.x; acc.w += f.y;
    }
    for (; e < end; e++) {
        uint2 a = hp[(size_t)g_esrc[e] * 32 + lane];
        float2 f;
        f = __half22float2(*(__half2*)&a.x); acc.x += f.x; acc.y += f.y;
        f = __half22float2(*(__half2*)&a.y); acc.z += f.x; acc.w += f.y;
    }
    float nd = g_ndst[gw];
    float4 b4 = ((const float4*)bias)[lane];
    float4 o;
    o.x = fmaxf(acc.x * nd + b4.x, 0.f);
    o.y = fmaxf(acc.y * nd + b4.y, 0.f);
    o.z = fmaxf(acc.z * nd + b4.z, 0.f);
    o.w = fmaxf(acc.w * nd + b4.w, 0.f);
    if constexpr (sizeof(TOut) == 4) {
        ((float4*)out)[(size_t)gw * 32 + lane] = o;
    } else {
        uint2 p;
        *(__half2*)&p.x = __floats2half2_rn(o.x, o.y);
        *(__half2*)&p.y = __floats2half2_rn(o.z, o.w);
        ((uint2*)out)[(size_t)gw * 32 + lane] = p;
    }
}

// ---------------- HMMA (mma.sync bf16) GEMM: C = ns ⊙ (A @ W), fp16 out ----------------
#define GP 272                       // smem row pitch bytes (17*16: ldmatrix conflict-free)
#define SM_AHI 0
#define SM_ALO (128 * GP)
#define SM_WHI (2 * 128 * GP)
#define SM_WLO (3 * 128 * GP)
#define GEMM_SMEM (4 * 128 * GP)     // 139264 B

__device__ __forceinline__ void ldsm_x4(uint32_t* r, uint32_t addr) {
    asm volatile("ldmatrix.sync.aligned.m8n8.x4.shared.b16 {%0,%1,%2,%3}, [%4];"
                 : "=r"(r[0]), "=r"(r[1]), "=r"(r[2]), "=r"(r[3]) : "r"(addr));
}
__device__ __forceinline__ void ldsm_x2(uint32_t& r0, uint32_t& r1, uint32_t addr) {
    asm volatile("ldmatrix.sync.aligned.m8n8.x2.shared.b16 {%0,%1}, [%2];"
                 : "=r"(r0), "=r"(r1) : "r"(addr));
}
__device__ __forceinline__ void mma_bf16(float* c, const uint32_t* a, uint32_t b0, uint32_t b1) {
    asm volatile("mma.sync.aligned.m16n8k16.row.col.f32.bf16.bf16.f32 "
                 "{%0,%1,%2,%3}, {%4,%5,%6,%7}, {%8,%9}, {%0,%1,%2,%3};"
                 : "+f"(c[0]), "+f"(c[1]), "+f"(c[2]), "+f"(c[3])
                 : "r"(a[0]), "r"(a[1]), "r"(a[2]), "r"(a[3]), "r"(b0), "r"(b1));
}

__device__ __forceinline__ uint32_t pack_bf16(float a, float b) {
    __nv_bfloat16 ah = __float2bfloat16_rn(a);
    __nv_bfloat16 bh = __float2bfloat16_rn(b);
    return (uint32_t)__bfloat16_as_ushort(ah) | ((uint32_t)__bfloat16_as_ushort(bh) << 16);
}

template <typename TIn>
__global__ __launch_bounds__(256, 1)
void gemm_tc_kernel(const TIn* __restrict__ A,
                    const __nv_bfloat16* __restrict__ Whi,
                    const __nv_bfloat16* __restrict__ Wlo,
                    __half* __restrict__ C, int n) {
    extern __shared__ char sm[];
    uint32_t base = smem_u32(sm);
    const int tid = threadIdx.x;
    const int w = tid >> 5, lane = tid & 31;
    const int row0 = blockIdx.x * 128;

    // W tiles: 128 rows x 256B (16 uint4) each
    for (int i = tid; i < 2048; i += 256) {
        int rr = i >> 4, q = i & 15;
        *(uint4*)(sm + SM_WHI + rr * GP + q * 16) = ((const uint4*)Whi)[rr * 16 + q];
        *(uint4*)(sm + SM_WLO + rr * GP + q * 16) = ((const uint4*)Wlo)[rr * 16 + q];
    }
    // A tile: split to bf16 hi/lo (2 threads per row, 64 cols each)
    {
        int r = tid >> 1, half_sel = tid & 1;
        int gr = row0 + r;
        #pragma unroll
        for (int i = 0; i < 16; i++) {
            float4 v = make_float4(0.f, 0.f, 0.f, 0.f);
            if (gr < n) {
                if constexpr (sizeof(TIn) == 4) {
                    v = ((const float4*)((const float*)A + (size_t)gr * DD + half_sel * 64))[i];
                } else {
                    uint2 u = ((const uint2*)((const __half*)A + (size_t)gr * DD + half_sel * 64))[i];
                    float2 f01 = __half22float2(*(__half2*)&u.x);
                    float2 f23 = __half22float2(*(__half2*)&u.y);
                    v = make_float4(f01.x, f01.y, f23.x, f23.y);
                }
            }
            __nv_bfloat16 hx = __float2bfloat16_rn(v.x), hy = __float2bfloat16_rn(v.y);
            __nv_bfloat16 hz = __float2bfloat16_rn(v.z), hw = __float2bfloat16_rn(v.w);
            uint32_t hi01 = (uint32_t)__bfloat16_as_ushort(hx) | ((uint32_t)__bfloat16_as_ushort(hy) << 16);
            uint32_t hi23 = (uint32_t)__bfloat16_as_ushort(hz) | ((uint32_t)__bfloat16_as_ushort(hw) << 16);
            uint32_t lo01 = pack_bf16(v.x - __bfloat162float(hx), v.y - __bfloat162float(hy));
            uint32_t lo23 = pack_bf16(v.z - __bfloat162float(hz), v.w - __bfloat162float(hw));
            int koff = (half_sel * 64 + i * 4) * 2;
            *(uint2*)(sm + SM_AHI + r * GP + koff) = make_uint2(hi01, hi23);
            *(uint2*)(sm + SM_ALO + r * GP + koff) = make_uint2(lo01, lo23);
        }
    }
    __syncthreads();

    float acc[16][4];
    #pragma unroll
    for (int j = 0; j < 16; j++)
        #pragma unroll
        for (int q = 0; q < 4; q++) acc[j][q] = 0.f;

    int i4 = lane >> 3, l7 = lane & 7;
    uint32_t aRow = (uint32_t)(w * 16 + (i4 & 1) * 8 + l7);
    uint32_t aK8  = (uint32_t)((i4 >> 1) * 8);
    uint32_t aHi = base + SM_AHI + aRow * GP + aK8 * 2;
    uint32_t aLo = base + SM_ALO + aRow * GP + aK8 * 2;
    uint32_t wRow = (uint32_t)(lane & 7);
    uint32_t wK8  = (uint32_t)(((lane >> 3) & 1) * 8);
    uint32_t wHi = base + SM_WHI + wRow * GP + wK8 * 2;
    uint32_t wLo = base + SM_WLO + wRow * GP + wK8 * 2;

    #pragma unroll
    for (int kk = 0; kk < 8; kk++) {
        uint32_t ah[4], al[4];
        ldsm_x4(ah, aHi + kk * 32);
        ldsm_x4(al, aLo + kk * 32);
        #pragma unroll
        for (int j = 0; j < 16; j++) {
            uint32_t bh0, bh1, bl0, bl1;
            ldsm_x2(bh0, bh1, wHi + j * 8 * GP + kk * 32);
            ldsm_x2(bl0, bl1, wLo + j * 8 * GP + kk * 32);
            mma_bf16(acc[j], ah, bh0, bh1);
            mma_bf16(acc[j], ah, bl0, bl1);
            mma_bf16(acc[j], al, bh0, bh1);
        }
    }

    // epilogue: scale rows by ns, write fp16
    int r0 = row0 + w * 16 + (lane >> 2);
    int c0 = (lane & 3) * 2;
    float ns0 = (r0 < n) ? g_nsrc[r0] : 0.f;
    float ns1 = (r0 + 8 < n) ? g_nsrc[r0 + 8] : 0.f;
    #pragma unroll
    for (int j = 0; j < 16; j++) {
        int nn = j * 8 + c0;
        if (r0 < n)
            *(__half2*)(C + (size_t)r0 * DD + nn) = __floats2half2_rn(acc[j][0] * ns0, acc[j][1] * ns0);
        if (r0 + 8 < n)
            *(__half2*)(C + (size_t)(r0 + 8) * DD + nn) = __floats2half2_rn(acc[j][2] * ns1, acc[j][3] * ns1);
    }
}

// ---------------- launch ----------------
extern "C" void kernel_launch(void* const* d_in, const int* in_sizes, int n_in,
                              void* d_out, int out_size) {
    const float* features = (const float*)d_in[0];
    const int*   src      = (const int*)d_in[1];   // jnp.int64 downgrades to int32 (x64 off)
    const int*   dst      = (const int*)d_in[2];
    const float* W1       = (const float*)d_in[3];
    const float* b1       = (const float*)d_in[4];
    const float* W2       = (const float*)d_in[5];
    const float* b2       = (const float*)d_in[6];
    float*       out      = (float*)d_out;

    int n = in_sizes[0] / DD;   // 100000
    int E = in_sizes[1];        // 1600000

    __half *G, *h1;
    __nv_bfloat16 *whi1, *wlo1, *whi2, *wlo2;
    cudaGetSymbolAddress((void**)&G, g_G);
    cudaGetSymbolAddress((void**)&h1, g_h1);
    cudaGetSymbolAddress((void**)&whi1, g_Whi1);
    cudaGetSymbolAddress((void**)&wlo1, g_Wlo1);
    cudaGetSymbolAddress((void**)&whi2, g_Whi2);
    cudaGetSymbolAddress((void**)&wlo2, g_Wlo2);

    cudaFuncSetAttribute(gemm_tc_kernel<float>,
                         cudaFuncAttributeMaxDynamicSharedMemorySize, GEMM_SMEM);
    cudaFuncSetAttribute(gemm_tc_kernel<__half>,
                         cudaFuncAttributeMaxDynamicSharedMemorySize, GEMM_SMEM);

    int tb = 256;
    int gN = (n + tb - 1) / tb;
    int gE = (E + tb - 1) / tb;
    int gSp = ((n * 32) + tb - 1) / tb;
    int gGemm = (n + 127) / 128;
    int B = (n + SCAN_CHUNK - 1) / SCAN_CHUNK;

    // degrees + norms first (gemm epilogue needs ns)
    zero_deg_kernel<<<gN, tb>>>(n);
    count_deg_kernel<<<gE, tb>>>(src, dst, E, n);
    norm_kernel<<<gN, tb>>>(n);
    wconv_kernel<<<64, 256>>>(W1, whi1, wlo1);
    wconv_kernel<<<64, 256>>>(W2, whi2, wlo2);

    // GEMM1 = ns ⊙ (features @ W1)  (independent of CSR)
    gemm_tc_kernel<float><<<gGemm, 256, GEMM_SMEM>>>(features, whi1, wlo1, G, n);

    // CSR build
    scan_reduce_kernel<<<B, 256>>>(n);
    scan_partials_kernel<<<1, 128>>>(B, E);
    scan_down_kernel<<<B, 256>>>(n);
    fill_csr_kernel<<<gE, tb>>>(src, dst, E, n);

    // layer 1 aggregation (+ nd, bias, relu fused) -> h1 (fp16)
    spmm_kernel<__half><<<gSp, tb>>>(G, b1, h1, n);
    // layer 2
    gemm_tc_kernel<__half><<<gGemm, 256, GEMM_SMEM>>>(h1, whi2, wlo2, G, n);
    spmm_kernel<float><<<gSp, tb>>>(G, b2, out, n);
}

// round 8
// speedup vs baseline: 1.5604x; 1.0837x over previous
#include <cuda_runtime.h>
#include <cuda_bf16.h>
#include <cuda_fp16.h>
#include <cstdint>

#define NN 100000
#define EE 1600000
#define DD 128
#define SCAN_CHUNK 1024
#define SCAN_B ((NN + SCAN_CHUNK - 1) / SCAN_CHUNK)   // 98

// ---------------- static device scratch (no allocations allowed) ----------------
__device__ int    g_outdeg[NN];
__device__ int    g_indeg[NN];
__device__ float  g_nsrc[NN];
__device__ float  g_ndst[NN];
__device__ int    g_off[NN + 1];
__device__ int    g_cur[NN];
__device__ int    g_part[SCAN_B + 1];
__device__ int    g_esrc[EE];
__device__ __half g_G[(size_t)NN * DD];    // ns-scaled GEMM output (gather source)
__device__ __half g_h1[(size_t)NN * DD];   // layer-1 activations
__device__ __nv_bfloat16 g_Whi1[DD * DD];  // W1 split (bf16, for fp32-A 3-pass)
__device__ __nv_bfloat16 g_Wlo1[DD * DD];
__device__ __half        g_Whi2[DD * DD];  // W2 split (fp16, for fp16-A 2-pass)
__device__ __half        g_Wlo2[DD * DD];

__device__ __forceinline__ uint32_t smem_u32(const void* p) {
    uint32_t a;
    asm("{ .reg .u64 t; cvta.to.shared.u64 t, %1; cvt.u32.u64 %0, t; }" : "=r"(a) : "l"(p));
    return a;
}

// ---------------- fused setup: zero degrees + split/transpose both W ----------------
__global__ __launch_bounds__(256)
void setup_kernel(const float* __restrict__ W1, const float* __restrict__ W2, int n) {
    int i = blockIdx.x * blockDim.x + threadIdx.x;
    if (i < n) { g_outdeg[i] = 0; g_indeg[i] = 0; }
    if (i < DD * DD) {
        // W1 -> bf16 hi/lo transposed
        int k = i >> 7, nn = i & 127;
        float w = W1[i];
        __nv_bfloat16 h = __float2bfloat16_rn(w);
        g_Whi1[nn * DD + k] = h;
        g_Wlo1[nn * DD + k] = __float2bfloat16_rn(w - __bfloat162float(h));
        // W2 -> fp16 hi/lo transposed
        float w2 = W2[i];
        __half h2 = __float2half_rn(w2);
        g_Whi2[nn * DD + k] = h2;
        g_Wlo2[nn * DD + k] = __float2half_rn(w2 - __half2float(h2));
    }
}

// 2 edges per thread
__global__ __launch_bounds__(256)
void count_deg_kernel(const int* __restrict__ src, const int* __restrict__ dst,
                      int E2, int E, int n) {
    int t = blockIdx.x * blockDim.x + threadIdx.x;
    if (t < E2) {
        int e = t * 2;
        if (e + 1 < E) {
            int2 s = *(const int2*)(src + e);
            int2 d = *(const int2*)(dst + e);
            if ((unsigned)s.x < (unsigned)n) atomicAdd(&g_outdeg[s.x], 1);
            if ((unsigned)s.y < (unsigned)n) atomicAdd(&g_outdeg[s.y], 1);
            if ((unsigned)d.x < (unsigned)n) atomicAdd(&g_indeg[d.x], 1);
            if ((unsigned)d.y < (unsigned)n) atomicAdd(&g_indeg[d.y], 1);
        } else {
            int s = src[e], d = dst[e];
            if ((unsigned)s < (unsigned)n) atomicAdd(&g_outdeg[s], 1);
            if ((unsigned)d < (unsigned)n) atomicAdd(&g_indeg[d], 1);
        }
    }
}

// ---- scan pass 1 (+ fused norm computation) ----
__global__ __launch_bounds__(256)
void scan_reduce_kernel(int n) {
    __shared__ int wsum[8];
    int b = blockIdx.x;
    int tid = threadIdx.x;
    int idx = b * SCAN_CHUNK + tid * 4;
    int s = 0;
    #pragma unroll
    for (int t = 0; t < 4; t++)
        if (idx + t < n) {
            int ind = g_indeg[idx + t];
            s += ind;
            g_ndst[idx + t] = rsqrtf(fmaxf((float)ind, 1.0f));
            g_nsrc[idx + t] = rsqrtf(fmaxf((float)g_outdeg[idx + t], 1.0f));
        }
    #pragma unroll
    for (int o = 16; o > 0; o >>= 1) s += __shfl_down_sync(0xffffffffu, s, o);
    int lane = tid & 31, wid = tid >> 5;
    if (lane == 0) wsum[wid] = s;
    __syncthreads();
    if (tid == 0) {
        int t = 0;
        #pragma unroll
        for (int w = 0; w < 8; w++) t += wsum[w];
        g_part[b] = t;
    }
}

__global__ __launch_bounds__(128)
void scan_partials_kernel(int B, int E) {
    __shared__ int sdata[128];
    int tid = threadIdx.x;
    int v = (tid < B) ? g_part[tid] : 0;
    sdata[tid] = v;
    __syncthreads();
    #pragma unroll
    for (int o = 1; o < 128; o <<= 1) {
        int t = (tid >= o) ? sdata[tid - o] : 0;
        __syncthreads();
        sdata[tid] += t;
        __syncthreads();
    }
    if (tid < B) g_part[tid] = sdata[tid] - v;
    if (tid == 0) g_off[NN] = E;
}

__global__ __launch_bounds__(256)
void scan_down_kernel(int n) {
    __shared__ int wscan[8];
    int b = blockIdx.x;
    int tid = threadIdx.x;
    int lane = tid & 31, wid = tid >> 5;
    int idx = b * SCAN_CHUNK + tid * 4;
    int v0 = 0, v1 = 0, v2 = 0, v3 = 0;
    if (idx + 0 < n) v0 = g_indeg[idx + 0];
    if (idx + 1 < n) v1 = g_indeg[idx + 1];
    if (idx + 2 < n) v2 = g_indeg[idx + 2];
    if (idx + 3 < n) v3 = g_indeg[idx + 3];
    int tsum = v0 + v1 + v2 + v3;
    int x = tsum;
    #pragma unroll
    for (int o = 1; o < 32; o <<= 1) {
        int y = __shfl_up_sync(0xffffffffu, x, o);
        if (lane >= o) x += y;
    }
    if (lane == 31) wscan[wid] = x;
    __syncthreads();
    if (wid == 0 && lane < 8) {
        int s = wscan[lane];
        #pragma unroll
        for (int o = 1; o < 8; o <<= 1) {
            int y = __shfl_up_sync(0x000000ffu, s, o);
            if (lane >= o) s += y;
        }
        wscan[lane] = s;
    }
    __syncthreads();
    int base = g_part[b] + (wid ? wscan[wid - 1] : 0) + (x - tsum);
    if (idx + 0 < n) { g_off[idx + 0] = base;            g_cur[idx + 0] = base; }
    if (idx + 1 < n) { g_off[idx + 1] = base + v0;       g_cur[idx + 1] = base + v0; }
    if (idx + 2 < n) { int t = base + v0 + v1;      g_off[idx + 2] = t; g_cur[idx + 2] = t; }
    if (idx + 3 < n) { int t = base + v0 + v1 + v2; g_off[idx + 3] = t; g_cur[idx + 3] = t; }
}

// 2 edges per thread
__global__ __launch_bounds__(256)
void fill_csr_kernel(const int* __restrict__ src, const int* __restrict__ dst,
                     int E2, int E, int n) {
    int t = blockIdx.x * blockDim.x + threadIdx.x;
    if (t < E2) {
        int e = t * 2;
        if (e + 1 < E) {
            int2 s = *(const int2*)(src + e);
            int2 d = *(const int2*)(dst + e);
            if ((unsigned)s.x < (unsigned)n && (unsigned)d.x < (unsigned)n)
                g_esrc[atomicAdd(&g_cur[d.x], 1)] = s.x;
            if ((unsigned)s.y < (unsigned)n && (unsigned)d.y < (unsigned)n)
                g_esrc[atomicAdd(&g_cur[d.y], 1)] = s.y;
        } else {
            int s = src[e], d = dst[e];
            if ((unsigned)s < (unsigned)n && (unsigned)d < (unsigned)n)
                g_esrc[atomicAdd(&g_cur[d], 1)] = s;
        }
    }
}

// ---------------- pull-based SpMM (fp16 gather) + fused nd/bias/relu ----------------
template <typename TOut>
__global__ __launch_bounds__(256)
void spmm_kernel(const __half* __restrict__ G, const float* __restrict__ bias,
                 TOut* __restrict__ out, int n) {
    int gw = (blockIdx.x * blockDim.x + threadIdx.x) >> 5;
    if (gw >= n) return;
    int lane = threadIdx.x & 31;
    int beg = g_off[gw];
    int end = g_off[gw + 1];
    const uint2* hp = (const uint2*)G;
    float4 acc = make_float4(0.f, 0.f, 0.f, 0.f);
    int e = beg;
    for (; e + 3 < end; e += 4) {
        int u0 = g_esrc[e], u1 = g_esrc[e + 1], u2 = g_esrc[e + 2], u3 = g_esrc[e + 3];
        uint2 a = hp[(size_t)u0 * 32 + lane];
        uint2 b = hp[(size_t)u1 * 32 + lane];
        uint2 c = hp[(size_t)u2 * 32 + lane];
        uint2 d = hp[(size_t)u3 * 32 + lane];
        float2 f;
        f = __half22float2(*(__half2*)&a.x); acc.x += f.x; acc.y += f.y;
        f = __half22float2(*(__half2*)&a.y); acc.z += f.x; acc.w += f.y;
        f = __half22float2(*(__half2*)&b.x); acc.x += f.x; acc.y += f.y;
        f = __half22float2(*(__half2*)&b.y); acc.z += f.x; acc.w += f.y;
        f = __half22float2(*(__half2*)&c.x); acc.x += f.x; acc.y += f.y;
        f = __half22float2(*(__half2*)&c.y); acc.z += f.x; acc.w += f.y;
        f = __half22float2(*(__half2*)&d.x); acc.x += f.x; acc.y += f.y;
        f = __half22float2(*(__half2*)&d.y); acc.z += f.x; acc.w += f.y;
    }
    for (; e < end; e++) {
        uint2 a = hp[(size_t)g_esrc[e] * 32 + lane];
        float2 f;
        f = __half22float2(*(__half2*)&a.x); acc.x += f.x; acc.y += f.y;
        f = __half22float2(*(__half2*)&a.y); acc.z += f.x; acc.w += f.y;
    }
    float nd = g_ndst[gw];
    float4 b4 = ((const float4*)bias)[lane];
    float4 o;
    o.x = fmaxf(acc.x * nd + b4.x, 0.f);
    o.y = fmaxf(acc.y * nd + b4.y, 0.f);
    o.z = fmaxf(acc.z * nd + b4.z, 0.f);
    o.w = fmaxf(acc.w * nd + b4.w, 0.f);
    if constexpr (sizeof(TOut) == 4) {
        ((float4*)out)[(size_t)gw * 32 + lane] = o;
    } else {
        uint2 p;
        *(__half2*)&p.x = __floats2half2_rn(o.x, o.y);
        *(__half2*)&p.y = __floats2half2_rn(o.z, o.w);
        ((uint2*)out)[(size_t)gw * 32 + lane] = p;
    }
}

// ---------------- HMMA GEMM: C = ns ⊙ (A @ W), fp16 out ----------------
// MODE 0: A fp32, W bf16 hi/lo, 3 passes.  MODE 1: A fp16 (exact), W fp16 hi/lo, 2 passes.
#define GP 272
#define SM_AHI 0
#define SM_ALO (128 * GP)
#define SM_WHI (2 * 128 * GP)
#define SM_WLO (3 * 128 * GP)
#define GEMM_SMEM (4 * 128 * GP)     // 139264 B

__device__ __forceinline__ void ldsm_x4(uint32_t* r, uint32_t addr) {
    asm volatile("ldmatrix.sync.aligned.m8n8.x4.shared.b16 {%0,%1,%2,%3}, [%4];"
                 : "=r"(r[0]), "=r"(r[1]), "=r"(r[2]), "=r"(r[3]) : "r"(addr));
}
__device__ __forceinline__ void ldsm_x2(uint32_t& r0, uint32_t& r1, uint32_t addr) {
    asm volatile("ldmatrix.sync.aligned.m8n8.x2.shared.b16 {%0,%1}, [%2];"
                 : "=r"(r0), "=r"(r1) : "r"(addr));
}
__device__ __forceinline__ void mma_bf16(float* c, const uint32_t* a, uint32_t b0, uint32_t b1) {
    asm volatile("mma.sync.aligned.m16n8k16.row.col.f32.bf16.bf16.f32 "
                 "{%0,%1,%2,%3}, {%4,%5,%6,%7}, {%8,%9}, {%0,%1,%2,%3};"
                 : "+f"(c[0]), "+f"(c[1]), "+f"(c[2]), "+f"(c[3])
                 : "r"(a[0]), "r"(a[1]), "r"(a[2]), "r"(a[3]), "r"(b0), "r"(b1));
}
__device__ __forceinline__ void mma_f16(float* c, const uint32_t* a, uint32_t b0, uint32_t b1) {
    asm volatile("mma.sync.aligned.m16n8k16.row.col.f32.f16.f16.f32 "
                 "{%0,%1,%2,%3}, {%4,%5,%6,%7}, {%8,%9}, {%0,%1,%2,%3};"
                 : "+f"(c[0]), "+f"(c[1]), "+f"(c[2]), "+f"(c[3])
                 : "r"(a[0]), "r"(a[1]), "r"(a[2]), "r"(a[3]), "r"(b0), "r"(b1));
}

__device__ __forceinline__ uint32_t pack_bf16(float a, float b) {
    __nv_bfloat16 ah = __float2bfloat16_rn(a);
    __nv_bfloat16 bh = __float2bfloat16_rn(b);
    return (uint32_t)__bfloat16_as_ushort(ah) | ((uint32_t)__bfloat16_as_ushort(bh) << 16);
}

template <int MODE>
__global__ __launch_bounds__(256, 1)
void gemm_tc_kernel(const void* __restrict__ Av,
                    const void* __restrict__ Whi,
                    const void* __restrict__ Wlo,
                    __half* __restrict__ C, int n) {
    extern __shared__ char sm[];
    uint32_t base = smem_u32(sm);
    const int tid = threadIdx.x;
    const int w = tid >> 5, lane = tid & 31;
    const int row0 = blockIdx.x * 128;

    // W tiles: 128 rows x 256B (dtype-agnostic byte copy)
    for (int i = tid; i < 2048; i += 256) {
        int rr = i >> 4, q = i & 15;
        *(uint4*)(sm + SM_WHI + rr * GP + q * 16) = ((const uint4*)Whi)[rr * 16 + q];
        *(uint4*)(sm + SM_WLO + rr * GP + q * 16) = ((const uint4*)Wlo)[rr * 16 + q];
    }
    // A tile
    {
        int r = tid >> 1, half_sel = tid & 1;
        int gr = row0 + r;
        if constexpr (MODE == 0) {
            // fp32 -> bf16 hi/lo split
            #pragma unroll
            for (int i = 0; i < 16; i++) {
                float4 v = make_float4(0.f, 0.f, 0.f, 0.f);
                if (gr < n)
                    v = ((const float4*)((const float*)Av + (size_t)gr * DD + half_sel * 64))[i];
                __nv_bfloat16 hx = __float2bfloat16_rn(v.x), hy = __float2bfloat16_rn(v.y);
                __nv_bfloat16 hz = __float2bfloat16_rn(v.z), hw = __float2bfloat16_rn(v.w);
                uint32_t hi01 = (uint32_t)__bfloat16_as_ushort(hx) | ((uint32_t)__bfloat16_as_ushort(hy) << 16);
                uint32_t hi23 = (uint32_t)__bfloat16_as_ushort(hz) | ((uint32_t)__bfloat16_as_ushort(hw) << 16);
                uint32_t lo01 = pack_bf16(v.x - __bfloat162float(hx), v.y - __bfloat162float(hy));
                uint32_t lo23 = pack_bf16(v.z - __bfloat162float(hz), v.w - __bfloat162float(hw));
                int koff = (half_sel * 64 + i * 4) * 2;
                *(uint2*)(sm + SM_AHI + r * GP + koff) = make_uint2(hi01, hi23);
                *(uint2*)(sm + SM_ALO + r * GP + koff) = make_uint2(lo01, lo23);
            }
        } else {
            // fp16: exact raw copy (no split needed)
            const uint4* ap = (const uint4*)((const __half*)Av + (size_t)gr * DD + half_sel * 64);
            #pragma unroll
            for (int i = 0; i < 8; i++) {
                uint4 v = make_uint4(0u, 0u, 0u, 0u);
                if (gr < n) v = ap[i];
                *(uint4*)(sm + SM_AHI + r * GP + half_sel * 128 + i * 16) = v;
            }
        }
    }
    __syncthreads();

    float acc[16][4];
    #pragma unroll
    for (int j = 0; j < 16; j++)
        #pragma unroll
        for (int q = 0; q < 4; q++) acc[j][q] = 0.f;

    int i4 = lane >> 3, l7 = lane & 7;
    uint32_t aRow = (uint32_t)(w * 16 + (i4 & 1) * 8 + l7);
    uint32_t aK8  = (uint32_t)((i4 >> 1) * 8);
    uint32_t aHi = base + SM_AHI + aRow * GP + aK8 * 2;
    uint32_t aLo = base + SM_ALO + aRow * GP + aK8 * 2;
    uint32_t wRow = (uint32_t)(lane & 7);
    uint32_t wK8  = (uint32_t)(((lane >> 3) & 1) * 8);
    uint32_t wHi = base + SM_WHI + wRow * GP + wK8 * 2;
    uint32_t wLo = base + SM_WLO + wRow * GP + wK8 * 2;

    #pragma unroll
    for (int kk = 0; kk < 8; kk++) {
        uint32_t ah[4], al[4];
        ldsm_x4(ah, aHi + kk * 32);
        if constexpr (MODE == 0) ldsm_x4(al, aLo + kk * 32);
        #pragma unroll
        for (int j = 0; j < 16; j++) {
            uint32_t bh0, bh1, bl0, bl1;
            ldsm_x2(bh0, bh1, wHi + j * 8 * GP + kk * 32);
            ldsm_x2(bl0, bl1, wLo + j * 8 * GP + kk * 32);
            if constexpr (MODE == 0) {
                mma_bf16(acc[j], ah, bh0, bh1);
                mma_bf16(acc[j], ah, bl0, bl1);
                mma_bf16(acc[j], al, bh0, bh1);
            } else {
                mma_f16(acc[j], ah, bh0, bh1);
                mma_f16(acc[j], ah, bl0, bl1);
            }
        }
    }

    // epilogue: scale rows by ns, write fp16
    int r0 = row0 + w * 16 + (lane >> 2);
    int c0 = (lane & 3) * 2;
    float ns0 = (r0 < n) ? g_nsrc[r0] : 0.f;
    float ns1 = (r0 + 8 < n) ? g_nsrc[r0 + 8] : 0.f;
    #pragma unroll
    for (int j = 0; j < 16; j++) {
        int nn = j * 8 + c0;
        if (r0 < n)
            *(__half2*)(C + (size_t)r0 * DD + nn) = __floats2half2_rn(acc[j][0] * ns0, acc[j][1] * ns0);
        if (r0 + 8 < n)
            *(__half2*)(C + (size_t)(r0 + 8) * DD + nn) = __floats2half2_rn(acc[j][2] * ns1, acc[j][3] * ns1);
    }
}

// ---------------- launch ----------------
extern "C" void kernel_launch(void* const* d_in, const int* in_sizes, int n_in,
                              void* d_out, int out_size) {
    const float* features = (const float*)d_in[0];
    const int*   src      = (const int*)d_in[1];   // jnp.int64 downgrades to int32 (x64 off)
    const int*   dst      = (const int*)d_in[2];
    const float* W1       = (const float*)d_in[3];
    const float* b1       = (const float*)d_in[4];
    const float* W2       = (const float*)d_in[5];
    const float* b2       = (const float*)d_in[6];
    float*       out      = (float*)d_out;

    int n = in_sizes[0] / DD;   // 100000
    int E = in_sizes[1];        // 1600000

    __half *G, *h1;
    __nv_bfloat16 *whi1, *wlo1;
    __half *whi2, *wlo2;
    cudaGetSymbolAddress((void**)&G, g_G);
    cudaGetSymbolAddress((void**)&h1, g_h1);
    cudaGetSymbolAddress((void**)&whi1, g_Whi1);
    cudaGetSymbolAddress((void**)&wlo1, g_Wlo1);
    cudaGetSymbolAddress((void**)&whi2, g_Whi2);
    cudaGetSymbolAddress((void**)&wlo2, g_Wlo2);

    cudaFuncSetAttribute(gemm_tc_kernel<0>,
                         cudaFuncAttributeMaxDynamicSharedMemorySize, GEMM_SMEM);
    cudaFuncSetAttribute(gemm_tc_kernel<1>,
                         cudaFuncAttributeMaxDynamicSharedMemorySize, GEMM_SMEM);

    int tb = 256;
    int gN = (n + tb - 1) / tb;
    int E2 = (E + 1) / 2;
    int gE2 = (E2 + tb - 1) / tb;
    int gSp = ((n * 32) + tb - 1) / tb;
    int gGemm = (n + 127) / 128;
    int B = (n + SCAN_CHUNK - 1) / SCAN_CHUNK;

    setup_kernel<<<gN, tb>>>(W1, W2, n);                    // zero degs + both W splits
    count_deg_kernel<<<gE2, tb>>>(src, dst, E2, E, n);
    scan_reduce_kernel<<<B, 256>>>(n);                      // + norms
    gemm_tc_kernel<0><<<gGemm, 256, GEMM_SMEM>>>(features, whi1, wlo1, G, n);
    scan_partials_kernel<<<1, 128>>>(B, E);
    scan_down_kernel<<<B, 256>>>(n);
    fill_csr_kernel<<<gE2, tb>>>(src, dst, E2, E, n);

    spmm_kernel<__half><<<gSp, tb>>>(G, b1, h1, n);
    gemm_tc_kernel<1><<<gGemm, 256, GEMM_SMEM>>>(h1, whi2, wlo2, G, n);
    spmm_kernel<float><<<gSp, tb>>>(G, b2, out, n);
}

// round 9
// speedup vs baseline: 1.6167x; 1.0361x over previous
#include <cuda_runtime.h>
#include <cuda_bf16.h>
#include <cuda_fp16.h>
#include <cstdint>

#define NN 100000
#define EE 1600000
#define DD 128
#define SCAN_CHUNK 1024
#define SCAN_B ((NN + SCAN_CHUNK - 1) / SCAN_CHUNK)   // 98

// ---------------- static device scratch (no allocations allowed) ----------------
__device__ int    g_outdeg[NN];
__device__ int    g_indeg[NN];
__device__ float  g_nsrc[NN];
__device__ float  g_ndst[NN];
__device__ int    g_off[NN + 1];
__device__ int    g_cur[NN];
__device__ int    g_part[SCAN_B + 1];
__device__ int    g_esrc[EE];
__device__ __half g_G[(size_t)NN * DD];    // ns-scaled GEMM output (gather source)
__device__ __half g_h1[(size_t)NN * DD];   // layer-1 activations
__device__ __nv_bfloat16 g_Whi1[DD * DD];  // W1 split (bf16, for fp32-A 3-pass)
__device__ __nv_bfloat16 g_Wlo1[DD * DD];
__device__ __half        g_Whi2[DD * DD];  // W2 split (fp16, for fp16-A 2-pass)
__device__ __half        g_Wlo2[DD * DD];

__device__ __forceinline__ uint32_t smem_u32(const void* p) {
    uint32_t a;
    asm("{ .reg .u64 t; cvta.to.shared.u64 t, %1; cvt.u32.u64 %0, t; }" : "=r"(a) : "l"(p));
    return a;
}

// ---------------- fused setup: zero degrees + split/transpose both W ----------------
__global__ __launch_bounds__(256)
void setup_kernel(const float* __restrict__ W1, const float* __restrict__ W2, int n) {
    int i = blockIdx.x * blockDim.x + threadIdx.x;
    if (i < n) { g_outdeg[i] = 0; g_indeg[i] = 0; }
    if (i < DD * DD) {
        int k = i >> 7, nn = i & 127;
        float w = W1[i];
        __nv_bfloat16 h = __float2bfloat16_rn(w);
        g_Whi1[nn * DD + k] = h;
        g_Wlo1[nn * DD + k] = __float2bfloat16_rn(w - __bfloat162float(h));
        float w2 = W2[i];
        __half h2 = __float2half_rn(w2);
        g_Whi2[nn * DD + k] = h2;
        g_Wlo2[nn * DD + k] = __float2half_rn(w2 - __half2float(h2));
    }
}

// 2 edges per thread
__global__ __launch_bounds__(256)
void count_deg_kernel(const int* __restrict__ src, const int* __restrict__ dst,
                      int E2, int E, int n) {
    int t = blockIdx.x * blockDim.x + threadIdx.x;
    if (t < E2) {
        int e = t * 2;
        if (e + 1 < E) {
            int2 s = *(const int2*)(src + e);
            int2 d = *(const int2*)(dst + e);
            if ((unsigned)s.x < (unsigned)n) atomicAdd(&g_outdeg[s.x], 1);
            if ((unsigned)s.y < (unsigned)n) atomicAdd(&g_outdeg[s.y], 1);
            if ((unsigned)d.x < (unsigned)n) atomicAdd(&g_indeg[d.x], 1);
            if ((unsigned)d.y < (unsigned)n) atomicAdd(&g_indeg[d.y], 1);
        } else {
            int s = src[e], d = dst[e];
            if ((unsigned)s < (unsigned)n) atomicAdd(&g_outdeg[s], 1);
            if ((unsigned)d < (unsigned)n) atomicAdd(&g_indeg[d], 1);
        }
    }
}

// ---- scan pass 1 (+ fused norm computation) ----
__global__ __launch_bounds__(256)
void scan_reduce_kernel(int n) {
    __shared__ int wsum[8];
    int b = blockIdx.x;
    int tid = threadIdx.x;
    int idx = b * SCAN_CHUNK + tid * 4;
    int s = 0;
    #pragma unroll
    for (int t = 0; t < 4; t++)
        if (idx + t < n) {
            int ind = g_indeg[idx + t];
            s += ind;
            g_ndst[idx + t] = rsqrtf(fmaxf((float)ind, 1.0f));
            g_nsrc[idx + t] = rsqrtf(fmaxf((float)g_outdeg[idx + t], 1.0f));
        }
    #pragma unroll
    for (int o = 16; o > 0; o >>= 1) s += __shfl_down_sync(0xffffffffu, s, o);
    int lane = tid & 31, wid = tid >> 5;
    if (lane == 0) wsum[wid] = s;
    __syncthreads();
    if (tid == 0) {
        int t = 0;
        #pragma unroll
        for (int w = 0; w < 8; w++) t += wsum[w];
        g_part[b] = t;
    }
}

__global__ __launch_bounds__(128)
void scan_partials_kernel(int B, int E) {
    __shared__ int sdata[128];
    int tid = threadIdx.x;
    int v = (tid < B) ? g_part[tid] : 0;
    sdata[tid] = v;
    __syncthreads();
    #pragma unroll
    for (int o = 1; o < 128; o <<= 1) {
        int t = (tid >= o) ? sdata[tid - o] : 0;
        __syncthreads();
        sdata[tid] += t;
        __syncthreads();
    }
    if (tid < B) g_part[tid] = sdata[tid] - v;
    if (tid == 0) g_off[NN] = E;
}

__global__ __launch_bounds__(256)
void scan_down_kernel(int n) {
    __shared__ int wscan[8];
    int b = blockIdx.x;
    int tid = threadIdx.x;
    int lane = tid & 31, wid = tid >> 5;
    int idx = b * SCAN_CHUNK + tid * 4;
    int v0 = 0, v1 = 0, v2 = 0, v3 = 0;
    if (idx + 0 < n) v0 = g_indeg[idx + 0];
    if (idx + 1 < n) v1 = g_indeg[idx + 1];
    if (idx + 2 < n) v2 = g_indeg[idx + 2];
    if (idx + 3 < n) v3 = g_indeg[idx + 3];
    int tsum = v0 + v1 + v2 + v3;
    int x = tsum;
    #pragma unroll
    for (int o = 1; o < 32; o <<= 1) {
        int y = __shfl_up_sync(0xffffffffu, x, o);
        if (lane >= o) x += y;
    }
    if (lane == 31) wscan[wid] = x;
    __syncthreads();
    if (wid == 0 && lane < 8) {
        int s = wscan[lane];
        #pragma unroll
        for (int o = 1; o < 8; o <<= 1) {
            int y = __shfl_up_sync(0x000000ffu, s, o);
            if (lane >= o) s += y;
        }
        wscan[lane] = s;
    }
    __syncthreads();
    int base = g_part[b] + (wid ? wscan[wid - 1] : 0) + (x - tsum);
    if (idx + 0 < n) { g_off[idx + 0] = base;            g_cur[idx + 0] = base; }
    if (idx + 1 < n) { g_off[idx + 1] = base + v0;       g_cur[idx + 1] = base + v0; }
    if (idx + 2 < n) { int t = base + v0 + v1;      g_off[idx + 2] = t; g_cur[idx + 2] = t; }
    if (idx + 3 < n) { int t = base + v0 + v1 + v2; g_off[idx + 3] = t; g_cur[idx + 3] = t; }
}

// 2 edges per thread
__global__ __launch_bounds__(256)
void fill_csr_kernel(const int* __restrict__ src, const int* __restrict__ dst,
                     int E2, int E, int n) {
    int t = blockIdx.x * blockDim.x + threadIdx.x;
    if (t < E2) {
        int e = t * 2;
        if (e + 1 < E) {
            int2 s = *(const int2*)(src + e);
            int2 d = *(const int2*)(dst + e);
            if ((unsigned)s.x < (unsigned)n && (unsigned)d.x < (unsigned)n)
                g_esrc[atomicAdd(&g_cur[d.x], 1)] = s.x;
            if ((unsigned)s.y < (unsigned)n && (unsigned)d.y < (unsigned)n)
                g_esrc[atomicAdd(&g_cur[d.y], 1)] = s.y;
        } else {
            int s = src[e], d = dst[e];
            if ((unsigned)s < (unsigned)n && (unsigned)d < (unsigned)n)
                g_esrc[atomicAdd(&g_cur[d], 1)] = s;
        }
    }
}

// ---------------- pull-based SpMM (fp16 gather) + fused nd/bias/relu ----------------
template <typename TOut>
__global__ __launch_bounds__(256)
void spmm_kernel(const __half* __restrict__ G, const float* __restrict__ bias,
                 TOut* __restrict__ out, int n) {
    int gw = (blockIdx.x * blockDim.x + threadIdx.x) >> 5;
    if (gw >= n) return;
    int lane = threadIdx.x & 31;
    int beg = g_off[gw];
    int end = g_off[gw + 1];
    const uint2* hp = (const uint2*)G;
    float4 acc = make_float4(0.f, 0.f, 0.f, 0.f);
    int e = beg;
    for (; e + 3 < end; e += 4) {
        int u0 = g_esrc[e], u1 = g_esrc[e + 1], u2 = g_esrc[e + 2], u3 = g_esrc[e + 3];
        uint2 a = hp[(size_t)u0 * 32 + lane];
        uint2 b = hp[(size_t)u1 * 32 + lane];
        uint2 c = hp[(size_t)u2 * 32 + lane];
        uint2 d = hp[(size_t)u3 * 32 + lane];
        float2 f;
        f = __half22float2(*(__half2*)&a.x); acc.x += f.x; acc.y += f.y;
        f = __half22float2(*(__half2*)&a.y); acc.z += f.x; acc.w += f.y;
        f = __half22float2(*(__half2*)&b.x); acc.x += f.x; acc.y += f.y;
        f = __half22float2(*(__half2*)&b.y); acc.z += f.x; acc.w += f.y;
        f = __half22float2(*(__half2*)&c.x); acc.x += f.x; acc.y += f.y;
        f = __half22float2(*(__half2*)&c.y); acc.z += f.x; acc.w += f.y;
        f = __half22float2(*(__half2*)&d.x); acc.x += f.x; acc.y += f.y;
        f = __half22float2(*(__half2*)&d.y); acc.z += f.x; acc.w += f.y;
    }
    for (; e < end; e++) {
        uint2 a = hp[(size_t)g_esrc[e] * 32 + lane];
        float2 f;
        f = __half22float2(*(__half2*)&a.x); acc.x += f.x; acc.y += f.y;
        f = __half22float2(*(__half2*)&a.y); acc.z += f.x; acc.w += f.y;
    }
    float nd = g_ndst[gw];
    float4 b4 = ((const float4*)bias)[lane];
    float4 o;
    o.x = fmaxf(acc.x * nd + b4.x, 0.f);
    o.y = fmaxf(acc.y * nd + b4.y, 0.f);
    o.z = fmaxf(acc.z * nd + b4.z, 0.f);
    o.w = fmaxf(acc.w * nd + b4.w, 0.f);
    if constexpr (sizeof(TOut) == 4) {
        ((float4*)out)[(size_t)gw * 32 + lane] = o;
    } else {
        uint2 p;
        *(__half2*)&p.x = __floats2half2_rn(o.x, o.y);
        *(__half2*)&p.y = __floats2half2_rn(o.z, o.w);
        ((uint2*)out)[(size_t)gw * 32 + lane] = p;
    }
}

// ---------------- HMMA GEMM: C = ns ⊙ (A @ W), fp16 out ----------------
// CTA tile: 256 rows x 128 cols; warp = 32 rows (2 MMA blocks); W frags via ldsm.x4.
// MODE 0: A fp32 -> bf16 hi/lo, 3 passes.  MODE 1: A fp16 exact, W fp16 hi/lo, 2 passes.
#define GP 272
#define TROWS 256

__device__ __forceinline__ void ldsm_x4(uint32_t* r, uint32_t addr) {
    asm volatile("ldmatrix.sync.aligned.m8n8.x4.shared.b16 {%0,%1,%2,%3}, [%4];"
                 : "=r"(r[0]), "=r"(r[1]), "=r"(r[2]), "=r"(r[3]) : "r"(addr));
}
__device__ __forceinline__ void mma_bf16(float* c, const uint32_t* a, uint32_t b0, uint32_t b1) {
    asm volatile("mma.sync.aligned.m16n8k16.row.col.f32.bf16.bf16.f32 "
                 "{%0,%1,%2,%3}, {%4,%5,%6,%7}, {%8,%9}, {%0,%1,%2,%3};"
                 : "+f"(c[0]), "+f"(c[1]), "+f"(c[2]), "+f"(c[3])
                 : "r"(a[0]), "r"(a[1]), "r"(a[2]), "r"(a[3]), "r"(b0), "r"(b1));
}
__device__ __forceinline__ void mma_f16(float* c, const uint32_t* a, uint32_t b0, uint32_t b1) {
    asm volatile("mma.sync.aligned.m16n8k16.row.col.f32.f16.f16.f32 "
                 "{%0,%1,%2,%3}, {%4,%5,%6,%7}, {%8,%9}, {%0,%1,%2,%3};"
                 : "+f"(c[0]), "+f"(c[1]), "+f"(c[2]), "+f"(c[3])
                 : "r"(a[0]), "r"(a[1]), "r"(a[2]), "r"(a[3]), "r"(b0), "r"(b1));
}
__device__ __forceinline__ uint32_t pack_bf16(float a, float b) {
    __nv_bfloat16 ah = __float2bfloat16_rn(a);
    __nv_bfloat16 bh = __float2bfloat16_rn(b);
    return (uint32_t)__bfloat16_as_ushort(ah) | ((uint32_t)__bfloat16_as_ushort(bh) << 16);
}

template <int MODE>
__global__ __launch_bounds__(256, 1)
void gemm_tc_kernel(const void* __restrict__ Av,
                    const void* __restrict__ Whi,
                    const void* __restrict__ Wlo,
                    __half* __restrict__ C, int n) {
    constexpr int SM_AHI_ = 0;
    constexpr int SM_ALO_ = TROWS * GP;                       // used only in MODE 0
    constexpr int SM_WHI_ = (MODE == 0) ? 2 * TROWS * GP : TROWS * GP;
    constexpr int SM_WLO_ = SM_WHI_ + 128 * GP;

    extern __shared__ char sm[];
    uint32_t base = smem_u32(sm);
    const int tid = threadIdx.x;
    const int w = tid >> 5, lane = tid & 31;
    const int row0 = blockIdx.x * TROWS;

    // W tiles: 128 rows x 256B
    for (int i = tid; i < 2048; i += 256) {
        int rr = i >> 4, q = i & 15;
        *(uint4*)(sm + SM_WHI_ + rr * GP + q * 16) = ((const uint4*)Whi)[rr * 16 + q];
        *(uint4*)(sm + SM_WLO_ + rr * GP + q * 16) = ((const uint4*)Wlo)[rr * 16 + q];
    }
    // A tile: one thread per row (256 rows)
    {
        int gr = row0 + tid;
        if constexpr (MODE == 0) {
            const float4* ap = (const float4*)((const float*)Av + (size_t)gr * DD);
            #pragma unroll
            for (int i = 0; i < 32; i++) {
                float4 v = make_float4(0.f, 0.f, 0.f, 0.f);
                if (gr < n) v = ap[i];
                __nv_bfloat16 hx = __float2bfloat16_rn(v.x), hy = __float2bfloat16_rn(v.y);
                __nv_bfloat16 hz = __float2bfloat16_rn(v.z), hw = __float2bfloat16_rn(v.w);
                uint32_t hi01 = (uint32_t)__bfloat16_as_ushort(hx) | ((uint32_t)__bfloat16_as_ushort(hy) << 16);
                uint32_t hi23 = (uint32_t)__bfloat16_as_ushort(hz) | ((uint32_t)__bfloat16_as_ushort(hw) << 16);
                uint32_t lo01 = pack_bf16(v.x - __bfloat162float(hx), v.y - __bfloat162float(hy));
                uint32_t lo23 = pack_bf16(v.z - __bfloat162float(hz), v.w - __bfloat162float(hw));
                *(uint2*)(sm + SM_AHI_ + tid * GP + i * 8) = make_uint2(hi01, hi23);
                *(uint2*)(sm + SM_ALO_ + tid * GP + i * 8) = make_uint2(lo01, lo23);
            }
        } else {
            const uint4* ap = (const uint4*)((const __half*)Av + (size_t)gr * DD);
            #pragma unroll
            for (int i = 0; i < 16; i++) {
                uint4 v = make_uint4(0u, 0u, 0u, 0u);
                if (gr < n) v = ap[i];
                *(uint4*)(sm + SM_AHI_ + tid * GP + i * 16) = v;
            }
        }
    }
    __syncthreads();

    float acc[2][16][4];
    #pragma unroll
    for (int b = 0; b < 2; b++)
        #pragma unroll
        for (int j = 0; j < 16; j++)
            #pragma unroll
            for (int q = 0; q < 4; q++) acc[b][j][q] = 0.f;

    // A lane addressing (ldsm x4, m16k16): two 16-row blocks per warp
    int i4 = lane >> 3, l7 = lane & 7;
    uint32_t aRowIn = (uint32_t)((i4 & 1) * 8 + l7);
    uint32_t aK8    = (uint32_t)((i4 >> 1) * 8);
    uint32_t aHi0 = base + SM_AHI_ + (w * 32 + aRowIn) * GP + aK8 * 2;
    uint32_t aHi1 = aHi0 + 16 * GP;
    uint32_t aLo0 = base + SM_ALO_ + (w * 32 + aRowIn) * GP + aK8 * 2;   // MODE 0 only
    uint32_t aLo1 = aLo0 + 16 * GP;
    // W lane addressing (ldsm x4 = a j-pair: 16 N-rows x k16)
    uint32_t wRow = (uint32_t)((lane & 7) + ((lane >> 4) << 3));
    uint32_t wK8  = (uint32_t)(((lane >> 3) & 1) * 8);
    uint32_t wHi = base + SM_WHI_ + wRow * GP + wK8 * 2;
    uint32_t wLo = base + SM_WLO_ + wRow * GP + wK8 * 2;

    #pragma unroll
    for (int kk = 0; kk < 8; kk++) {
        uint32_t ah0[4], ah1[4], al0[4], al1[4];
        ldsm_x4(ah0, aHi0 + kk * 32);
        ldsm_x4(ah1, aHi1 + kk * 32);
        if constexpr (MODE == 0) {
            ldsm_x4(al0, aLo0 + kk * 32);
            ldsm_x4(al1, aLo1 + kk * 32);
        }
        #pragma unroll
        for (int jj = 0; jj < 8; jj++) {
            uint32_t wh[4], wl[4];
            ldsm_x4(wh, wHi + jj * 16 * GP + kk * 32);
            ldsm_x4(wl, wLo + jj * 16 * GP + kk * 32);
            int j0 = 2 * jj, j1 = 2 * jj + 1;
            if constexpr (MODE == 0) {
                mma_bf16(acc[0][j0], ah0, wh[0], wh[1]);
                mma_bf16(acc[0][j1], ah0, wh[2], wh[3]);
                mma_bf16(acc[1][j0], ah1, wh[0], wh[1]);
                mma_bf16(acc[1][j1], ah1, wh[2], wh[3]);
                mma_bf16(acc[0][j0], ah0, wl[0], wl[1]);
                mma_bf16(acc[0][j1], ah0, wl[2], wl[3]);
                mma_bf16(acc[1][j0], ah1, wl[0], wl[1]);
                mma_bf16(acc[1][j1], ah1, wl[2], wl[3]);
                mma_bf16(acc[0][j0], al0, wh[0], wh[1]);
                mma_bf16(acc[0][j1], al0, wh[2], wh[3]);
                mma_bf16(acc[1][j0], al1, wh[0], wh[1]);
                mma_bf16(acc[1][j1], al1, wh[2], wh[3]);
            } else {
                mma_f16(acc[0][j0], ah0, wh[0], wh[1]);
                mma_f16(acc[0][j1], ah0, wh[2], wh[3]);
                mma_f16(acc[1][j0], ah1, wh[0], wh[1]);
                mma_f16(acc[1][j1], ah1, wh[2], wh[3]);
                mma_f16(acc[0][j0], ah0, wl[0], wl[1]);
                mma_f16(acc[0][j1], ah0, wl[2], wl[3]);
                mma_f16(acc[1][j0], ah1, wl[0], wl[1]);
                mma_f16(acc[1][j1], ah1, wl[2], wl[3]);
            }
        }
    }

    // epilogue: scale rows by ns, write fp16
    int c0 = (lane & 3) * 2;
    #pragma unroll
    for (int b = 0; b < 2; b++) {
        int r0 = row0 + w * 32 + b * 16 + (lane >> 2);
        float ns0 = (r0 < n) ? g_nsrc[r0] : 0.f;
        float ns1 = (r0 + 8 < n) ? g_nsrc[r0 + 8] : 0.f;
        #pragma unroll
        for (int j = 0; j < 16; j++) {
            int nn = j * 8 + c0;
            if (r0 < n)
                *(__half2*)(C + (size_t)r0 * DD + nn) = __floats2half2_rn(acc[b][j][0] * ns0, acc[b][j][1] * ns0);
            if (r0 + 8 < n)
                *(__half2*)(C + (size_t)(r0 + 8) * DD + nn) = __floats2half2_rn(acc[b][j][2] * ns1, acc[b][j][3] * ns1);
        }
    }
}

#define GEMM_SMEM0 ((2 * TROWS + 2 * 128) * GP)   // 208896
#define GEMM_SMEM1 ((TROWS + 2 * 128) * GP)       // 139264

// ---------------- launch ----------------
extern "C" void kernel_launch(void* const* d_in, const int* in_sizes, int n_in,
                              void* d_out, int out_size) {
    const float* features = (const float*)d_in[0];
    const int*   src      = (const int*)d_in[1];   // jnp.int64 downgrades to int32 (x64 off)
    const int*   dst      = (const int*)d_in[2];
    const float* W1       = (const float*)d_in[3];
    const float* b1       = (const float*)d_in[4];
    const float* W2       = (const float*)d_in[5];
    const float* b2       = (const float*)d_in[6];
    float*       out      = (float*)d_out;

    int n = in_sizes[0] / DD;   // 100000
    int E = in_sizes[1];        // 1600000

    __half *G, *h1;
    __nv_bfloat16 *whi1, *wlo1;
    __half *whi2, *wlo2;
    cudaGetSymbolAddress((void**)&G, g_G);
    cudaGetSymbolAddress((void**)&h1, g_h1);
    cudaGetSymbolAddress((void**)&whi1, g_Whi1);
    cudaGetSymbolAddress((void**)&wlo1, g_Wlo1);
    cudaGetSymbolAddress((void**)&whi2, g_Whi2);
    cudaGetSymbolAddress((void**)&wlo2, g_Wlo2);

    cudaFuncSetAttribute(gemm_tc_kernel<0>,
                         cudaFuncAttributeMaxDynamicSharedMemorySize, GEMM_SMEM0);
    cudaFuncSetAttribute(gemm_tc_kernel<1>,
                         cudaFuncAttributeMaxDynamicSharedMemorySize, GEMM_SMEM1);

    int tb = 256;
    int gN = (n + tb - 1) / tb;
    int E2 = (E + 1) / 2;
    int gE2 = (E2 + tb - 1) / tb;
    int gSp = ((n * 32) + tb - 1) / tb;
    int gGemm = (n + TROWS - 1) / TROWS;
    int B = (n + SCAN_CHUNK - 1) / SCAN_CHUNK;

    setup_kernel<<<gN, tb>>>(W1, W2, n);
    count_deg_kernel<<<gE2, tb>>>(src, dst, E2, E, n);
    scan_reduce_kernel<<<B, 256>>>(n);
    gemm_tc_kernel<0><<<gGemm, 256, GEMM_SMEM0>>>(features, whi1, wlo1, G, n);
    scan_partials_kernel<<<1, 128>>>(B, E);
    scan_down_kernel<<<B, 256>>>(n);
    fill_csr_kernel<<<gE2, tb>>>(src, dst, E2, E, n);

    spmm_kernel<__half><<<gSp, tb>>>(G, b1, h1, n);
    gemm_tc_kernel<1><<<gGemm, 256, GEMM_SMEM1>>>(h1, whi2, wlo2, G, n);
    spmm_kernel<float><<<gSp, tb>>>(G, b2, out, n);
}

// round 10
// speedup vs baseline: 1.6947x; 1.0482x over previous
#include <cuda_runtime.h>
#include <cuda_bf16.h>
#include <cuda_fp16.h>
#include <cstdint>

#define NN 100000
#define EE 1600000
#define DD 128
#define SCAN_CHUNK 1024
#define SCAN_B ((NN + SCAN_CHUNK - 1) / SCAN_CHUNK)   // 98

// ---------------- static device scratch (no allocations allowed) ----------------
__device__ int    g_outdeg[NN];
__device__ int    g_indeg[NN];
__device__ float  g_nsrc[NN];
__device__ float  g_ndst[NN];
__device__ int    g_off[NN + 1];
__device__ int    g_cur[NN];
__device__ int    g_part[SCAN_B + 1];
__device__ int    g_esrc[EE];
__device__ __half g_G[(size_t)NN * DD];    // ns-scaled GEMM output (gather source)
__device__ __half g_h1[(size_t)NN * DD];   // layer-1 activations
__device__ __half g_Whi1[DD * DD];         // W1 split (fp16 hi/lo, transposed)
__device__ __half g_Wlo1[DD * DD];
__device__ __half g_Whi2[DD * DD];         // W2 split (fp16 hi/lo, transposed)
__device__ __half g_Wlo2[DD * DD];

__device__ __forceinline__ uint32_t smem_u32(const void* p) {
    uint32_t a;
    asm("{ .reg .u64 t; cvta.to.shared.u64 t, %1; cvt.u32.u64 %0, t; }" : "=r"(a) : "l"(p));
    return a;
}

// ---------------- fused setup: zero degrees + split/transpose both W ----------------
__global__ __launch_bounds__(256)
void setup_kernel(const float* __restrict__ W1, const float* __restrict__ W2, int n) {
    int i = blockIdx.x * blockDim.x + threadIdx.x;
    if (i < n) { g_outdeg[i] = 0; g_indeg[i] = 0; }
    if (i < DD * DD) {
        int k = i >> 7, nn = i & 127;
        float w1 = W1[i];
        __half h1v = __float2half_rn(w1);
        g_Whi1[nn * DD + k] = h1v;
        g_Wlo1[nn * DD + k] = __float2half_rn(w1 - __half2float(h1v));
        float w2 = W2[i];
        __half h2 = __float2half_rn(w2);
        g_Whi2[nn * DD + k] = h2;
        g_Wlo2[nn * DD + k] = __float2half_rn(w2 - __half2float(h2));
    }
}

// 2 edges per thread
__global__ __launch_bounds__(256)
void count_deg_kernel(const int* __restrict__ src, const int* __restrict__ dst,
                      int E2, int E, int n) {
    int t = blockIdx.x * blockDim.x + threadIdx.x;
    if (t < E2) {
        int e = t * 2;
        if (e + 1 < E) {
            int2 s = *(const int2*)(src + e);
            int2 d = *(const int2*)(dst + e);
            if ((unsigned)s.x < (unsigned)n) atomicAdd(&g_outdeg[s.x], 1);
            if ((unsigned)s.y < (unsigned)n) atomicAdd(&g_outdeg[s.y], 1);
            if ((unsigned)d.x < (unsigned)n) atomicAdd(&g_indeg[d.x], 1);
            if ((unsigned)d.y < (unsigned)n) atomicAdd(&g_indeg[d.y], 1);
        } else {
            int s = src[e], d = dst[e];
            if ((unsigned)s < (unsigned)n) atomicAdd(&g_outdeg[s], 1);
            if ((unsigned)d < (unsigned)n) atomicAdd(&g_indeg[d], 1);
        }
    }
}

// ---- scan pass 1 (+ fused norm computation) ----
__global__ __launch_bounds__(256)
void scan_reduce_kernel(int n) {
    __shared__ int wsum[8];
    int b = blockIdx.x;
    int tid = threadIdx.x;
    int idx = b * SCAN_CHUNK + tid * 4;
    int s = 0;
    #pragma unroll
    for (int t = 0; t < 4; t++)
        if (idx + t < n) {
            int ind = g_indeg[idx + t];
            s += ind;
            g_ndst[idx + t] = rsqrtf(fmaxf((float)ind, 1.0f));
            g_nsrc[idx + t] = rsqrtf(fmaxf((float)g_outdeg[idx + t], 1.0f));
        }
    #pragma unroll
    for (int o = 16; o > 0; o >>= 1) s += __shfl_down_sync(0xffffffffu, s, o);
    int lane = tid & 31, wid = tid >> 5;
    if (lane == 0) wsum[wid] = s;
    __syncthreads();
    if (tid == 0) {
        int t = 0;
        #pragma unroll
        for (int w = 0; w < 8; w++) t += wsum[w];
        g_part[b] = t;
    }
}

__global__ __launch_bounds__(128)
void scan_partials_kernel(int B, int E) {
    __shared__ int sdata[128];
    int tid = threadIdx.x;
    int v = (tid < B) ? g_part[tid] : 0;
    sdata[tid] = v;
    __syncthreads();
    #pragma unroll
    for (int o = 1; o < 128; o <<= 1) {
        int t = (tid >= o) ? sdata[tid - o] : 0;
        __syncthreads();
        sdata[tid] += t;
        __syncthreads();
    }
    if (tid < B) g_part[tid] = sdata[tid] - v;
    if (tid == 0) g_off[NN] = E;
}

__global__ __launch_bounds__(256)
void scan_down_kernel(int n) {
    __shared__ int wscan[8];
    int b = blockIdx.x;
    int tid = threadIdx.x;
    int lane = tid & 31, wid = tid >> 5;
    int idx = b * SCAN_CHUNK + tid * 4;
    int v0 = 0, v1 = 0, v2 = 0, v3 = 0;
    if (idx + 0 < n) v0 = g_indeg[idx + 0];
    if (idx + 1 < n) v1 = g_indeg[idx + 1];
    if (idx + 2 < n) v2 = g_indeg[idx + 2];
    if (idx + 3 < n) v3 = g_indeg[idx + 3];
    int tsum = v0 + v1 + v2 + v3;
    int x = tsum;
    #pragma unroll
    for (int o = 1; o < 32; o <<= 1) {
        int y = __shfl_up_sync(0xffffffffu, x, o);
        if (lane >= o) x += y;
    }
    if (lane == 31) wscan[wid] = x;
    __syncthreads();
    if (wid == 0 && lane < 8) {
        int s = wscan[lane];
        #pragma unroll
        for (int o = 1; o < 8; o <<= 1) {
            int y = __shfl_up_sync(0x000000ffu, s, o);
            if (lane >= o) s += y;
        }
        wscan[lane] = s;
    }
    __syncthreads();
    int base = g_part[b] + (wid ? wscan[wid - 1] : 0) + (x - tsum);
    if (idx + 0 < n) { g_off[idx + 0] = base;            g_cur[idx + 0] = base; }
    if (idx + 1 < n) { g_off[idx + 1] = base + v0;       g_cur[idx + 1] = base + v0; }
    if (idx + 2 < n) { int t = base + v0 + v1;      g_off[idx + 2] = t; g_cur[idx + 2] = t; }
    if (idx + 3 < n) { int t = base + v0 + v1 + v2; g_off[idx + 3] = t; g_cur[idx + 3] = t; }
}

// 2 edges per thread
__global__ __launch_bounds__(256)
void fill_csr_kernel(const int* __restrict__ src, const int* __restrict__ dst,
                     int E2, int E, int n) {
    int t = blockIdx.x * blockDim.x + threadIdx.x;
    if (t < E2) {
        int e = t * 2;
        if (e + 1 < E) {
            int2 s = *(const int2*)(src + e);
            int2 d = *(const int2*)(dst + e);
            if ((unsigned)s.x < (unsigned)n && (unsigned)d.x < (unsigned)n)
                g_esrc[atomicAdd(&g_cur[d.x], 1)] = s.x;
            if ((unsigned)s.y < (unsigned)n && (unsigned)d.y < (unsigned)n)
                g_esrc[atomicAdd(&g_cur[d.y], 1)] = s.y;
        } else {
            int s = src[e], d = dst[e];
            if ((unsigned)s < (unsigned)n && (unsigned)d < (unsigned)n)
                g_esrc[atomicAdd(&g_cur[d], 1)] = s;
        }
    }
}

// ---------------- pull-based SpMM (fp16 gather) + fused nd/bias/relu ----------------
template <typename TOut>
__global__ __launch_bounds__(256)
void spmm_kernel(const __half* __restrict__ G, const float* __restrict__ bias,
                 TOut* __restrict__ out, int n) {
    int gw = (blockIdx.x * blockDim.x + threadIdx.x) >> 5;
    if (gw >= n) return;
    int lane = threadIdx.x & 31;
    int beg = g_off[gw];
    int end = g_off[gw + 1];
    const uint2* hp = (const uint2*)G;
    float4 acc = make_float4(0.f, 0.f, 0.f, 0.f);
    int e = beg;
    for (; e + 3 < end; e += 4) {
        int u0 = g_esrc[e], u1 = g_esrc[e + 1], u2 = g_esrc[e + 2], u3 = g_esrc[e + 3];
        uint2 a = hp[(size_t)u0 * 32 + lane];
        uint2 b = hp[(size_t)u1 * 32 + lane];
        uint2 c = hp[(size_t)u2 * 32 + lane];
        uint2 d = hp[(size_t)u3 * 32 + lane];
        float2 f;
        f = __half22float2(*(__half2*)&a.x); acc.x += f.x; acc.y += f.y;
        f = __half22float2(*(__half2*)&a.y); acc.z += f.x; acc.w += f.y;
        f = __half22float2(*(__half2*)&b.x); acc.x += f.x; acc.y += f.y;
        f = __half22float2(*(__half2*)&b.y); acc.z += f.x; acc.w += f.y;
        f = __half22float2(*(__half2*)&c.x); acc.x += f.x; acc.y += f.y;
        f = __half22float2(*(__half2*)&c.y); acc.z += f.x; acc.w += f.y;
        f = __half22float2(*(__half2*)&d.x); acc.x += f.x; acc.y += f.y;
        f = __half22float2(*(__half2*)&d.y); acc.z += f.x; acc.w += f.y;
    }
    for (; e < end; e++) {
        uint2 a = hp[(size_t)g_esrc[e] * 32 + lane];
        float2 f;
        f = __half22float2(*(__half2*)&a.x); acc.x += f.x; acc.y += f.y;
        f = __half22float2(*(__half2*)&a.y); acc.z += f.x; acc.w += f.y;
    }
    float nd = g_ndst[gw];
    float4 b4 = ((const float4*)bias)[lane];
    float4 o;
    o.x = fmaxf(acc.x * nd + b4.x, 0.f);
    o.y = fmaxf(acc.y * nd + b4.y, 0.f);
    o.z = fmaxf(acc.z * nd + b4.z, 0.f);
    o.w = fmaxf(acc.w * nd + b4.w, 0.f);
    if constexpr (sizeof(TOut) == 4) {
        ((float4*)out)[(size_t)gw * 32 + lane] = o;
    } else {
        uint2 p;
        *(__half2*)&p.x = __floats2half2_rn(o.x, o.y);
        *(__half2*)&p.y = __floats2half2_rn(o.z, o.w);
        ((uint2*)out)[(size_t)gw * 32 + lane] = p;
    }
}

// ---------------- HMMA GEMM: C = ns ⊙ (A @ W), fp16 out ----------------
// A -> single fp16 smem tile (fp32 converted on load); W fp16 hi/lo 2-pass.
// CTA: 128 rows, 256 thr, warp = 16 rows. smem 104.4KB -> 2 CTAs/SM.
#define GP 272
#define TROWS 128
#define SM_A   0
#define SM_WHI (TROWS * GP)
#define SM_WLO (SM_WHI + 128 * GP)
#define GEMM_SMEM ((TROWS + 2 * 128) * GP)   // 104448

__device__ __forceinline__ void ldsm_x4(uint32_t* r, uint32_t addr) {
    asm volatile("ldmatrix.sync.aligned.m8n8.x4.shared.b16 {%0,%1,%2,%3}, [%4];"
                 : "=r"(r[0]), "=r"(r[1]), "=r"(r[2]), "=r"(r[3]) : "r"(addr));
}
__device__ __forceinline__ void mma_f16(float* c, const uint32_t* a, uint32_t b0, uint32_t b1) {
    asm volatile("mma.sync.aligned.m16n8k16.row.col.f32.f16.f16.f32 "
                 "{%0,%1,%2,%3}, {%4,%5,%6,%7}, {%8,%9}, {%0,%1,%2,%3};"
                 : "+f"(c[0]), "+f"(c[1]), "+f"(c[2]), "+f"(c[3])
                 : "r"(a[0]), "r"(a[1]), "r"(a[2]), "r"(a[3]), "r"(b0), "r"(b1));
}

template <int AFP32>
__global__ __launch_bounds__(256, 2)
void gemm_tc_kernel(const void* __restrict__ Av,
                    const __half* __restrict__ Whi,
                    const __half* __restrict__ Wlo,
                    __half* __restrict__ C, int n) {
    extern __shared__ char sm[];
    uint32_t base = smem_u32(sm);
    const int tid = threadIdx.x;
    const int w = tid >> 5, lane = tid & 31;
    const int row0 = blockIdx.x * TROWS;

    // W tiles: 128 rows x 256B
    for (int i = tid; i < 2048; i += 256) {
        int rr = i >> 4, q = i & 15;
        *(uint4*)(sm + SM_WHI + rr * GP + q * 16) = ((const uint4*)Whi)[rr * 16 + q];
        *(uint4*)(sm + SM_WLO + rr * GP + q * 16) = ((const uint4*)Wlo)[rr * 16 + q];
    }
    // A tile (fp16), 2 threads per row x 64 cols
    {
        int r = tid >> 1, half_sel = tid & 1;
        int gr = row0 + r;
        if constexpr (AFP32) {
            const float4* ap = (const float4*)((const float*)Av + (size_t)gr * DD + half_sel * 64);
            #pragma unroll
            for (int i = 0; i < 16; i += 2) {
                float4 v0 = make_float4(0.f, 0.f, 0.f, 0.f);
                float4 v1 = make_float4(0.f, 0.f, 0.f, 0.f);
                if (gr < n) { v0 = ap[i]; v1 = ap[i + 1]; }
                uint4 pk;
                *(__half2*)&pk.x = __floats2half2_rn(v0.x, v0.y);
                *(__half2*)&pk.y = __floats2half2_rn(v0.z, v0.w);
                *(__half2*)&pk.z = __floats2half2_rn(v1.x, v1.y);
                *(__half2*)&pk.w = __floats2half2_rn(v1.z, v1.w);
                *(uint4*)(sm + SM_A + r * GP + half_sel * 128 + i * 8) = pk;
            }
        } else {
            const uint4* ap = (const uint4*)((const __half*)Av + (size_t)gr * DD + half_sel * 64);
            #pragma unroll
            for (int i = 0; i < 8; i++) {
                uint4 v = make_uint4(0u, 0u, 0u, 0u);
                if (gr < n) v = ap[i];
                *(uint4*)(sm + SM_A + r * GP + half_sel * 128 + i * 16) = v;
            }
        }
    }
    __syncthreads();

    float acc[16][4];
    #pragma unroll
    for (int j = 0; j < 16; j++)
        #pragma unroll
        for (int q = 0; q < 4; q++) acc[j][q] = 0.f;

    // A lane addressing (ldsm x4 = 16 rows x k16)
    int i4 = lane >> 3, l7 = lane & 7;
    uint32_t aRow = (uint32_t)(w * 16 + (i4 & 1) * 8 + l7);
    uint32_t aK8  = (uint32_t)((i4 >> 1) * 8);
    uint32_t aA = base + SM_A + aRow * GP + aK8 * 2;
    // W lane addressing (ldsm x4 = j-pair: 16 N-rows x k16)
    uint32_t wRow = (uint32_t)((lane & 7) + ((lane >> 4) << 3));
    uint32_t wK8  = (uint32_t)(((lane >> 3) & 1) * 8);
    uint32_t wHi = base + SM_WHI + wRow * GP + wK8 * 2;
    uint32_t wLo = base + SM_WLO + wRow * GP + wK8 * 2;

    #pragma unroll
    for (int kk = 0; kk < 8; kk++) {
        uint32_t ah[4];
        ldsm_x4(ah, aA + kk * 32);
        #pragma unroll
        for (int jj = 0; jj < 8; jj++) {
            uint32_t wh[4], wl[4];
            ldsm_x4(wh, wHi + jj * 16 * GP + kk * 32);
            ldsm_x4(wl, wLo + jj * 16 * GP + kk * 32);
            int j0 = 2 * jj, j1 = 2 * jj + 1;
            mma_f16(acc[j0], ah, wh[0], wh[1]);
            mma_f16(acc[j1], ah, wh[2], wh[3]);
            mma_f16(acc[j0], ah, wl[0], wl[1]);
            mma_f16(acc[j1], ah, wl[2], wl[3]);
        }
    }

    // epilogue: scale rows by ns, write fp16
    int c0 = (lane & 3) * 2;
    int r0 = row0 + w * 16 + (lane >> 2);
    float ns0 = (r0 < n) ? g_nsrc[r0] : 0.f;
    float ns1 = (r0 + 8 < n) ? g_nsrc[r0 + 8] : 0.f;
    #pragma unroll
    for (int j = 0; j < 16; j++) {
        int nn = j * 8 + c0;
        if (r0 < n)
            *(__half2*)(C + (size_t)r0 * DD + nn) = __floats2half2_rn(acc[j][0] * ns0, acc[j][1] * ns0);
        if (r0 + 8 < n)
            *(__half2*)(C + (size_t)(r0 + 8) * DD + nn) = __floats2half2_rn(acc[j][2] * ns1, acc[j][3] * ns1);
    }
}

// ---------------- launch ----------------
extern "C" void kernel_launch(void* const* d_in, const int* in_sizes, int n_in,
                              void* d_out, int out_size) {
    const float* features = (const float*)d_in[0];
    const int*   src      = (const int*)d_in[1];   // jnp.int64 downgrades to int32 (x64 off)
    const int*   dst      = (const int*)d_in[2];
    const float* W1       = (const float*)d_in[3];
    const float* b1       = (const float*)d_in[4];
    const float* W2       = (const float*)d_in[5];
    const float* b2       = (const float*)d_in[6];
    float*       out      = (float*)d_out;

    int n = in_sizes[0] / DD;   // 100000
    int E = in_sizes[1];        // 1600000

    __half *G, *h1, *whi1, *wlo1, *whi2, *wlo2;
    cudaGetSymbolAddress((void**)&G, g_G);
    cudaGetSymbolAddress((void**)&h1, g_h1);
    cudaGetSymbolAddress((void**)&whi1, g_Whi1);
    cudaGetSymbolAddress((void**)&wlo1, g_Wlo1);
    cudaGetSymbolAddress((void**)&whi2, g_Whi2);
    cudaGetSymbolAddress((void**)&wlo2, g_Wlo2);

    cudaFuncSetAttribute(gemm_tc_kernel<1>,
                         cudaFuncAttributeMaxDynamicSharedMemorySize, GEMM_SMEM);
    cudaFuncSetAttribute(gemm_tc_kernel<0>,
                         cudaFuncAttributeMaxDynamicSharedMemorySize, GEMM_SMEM);

    int tb = 256;
    int gN = (n + tb - 1) / tb;
    int E2 = (E + 1) / 2;
    int gE2 = (E2 + tb - 1) / tb;
    int gSp = ((n * 32) + tb - 1) / tb;
    int gGemm = (n + TROWS - 1) / TROWS;
    int B = (n + SCAN_CHUNK - 1) / SCAN_CHUNK;

    setup_kernel<<<gN, tb>>>(W1, W2, n);
    count_deg_kernel<<<gE2, tb>>>(src, dst, E2, E, n);
    scan_reduce_kernel<<<B, 256>>>(n);
    gemm_tc_kernel<1><<<gGemm, 256, GEMM_SMEM>>>(features, whi1, wlo1, G, n);
    scan_partials_kernel<<<1, 128>>>(B, E);
    scan_down_kernel<<<B, 256>>>(n);
    fill_csr_kernel<<<gE2, tb>>>(src, dst, E2, E, n);

    spmm_kernel<__half><<<gSp, tb>>>(G, b1, h1, n);
    gemm_tc_kernel<0><<<gGemm, 256, GEMM_SMEM>>>(h1, whi2, wlo2, G, n);
    spmm_kernel<float><<<gSp, tb>>>(G, b2, out, n);
}

// round 11
// speedup vs baseline: 1.7153x; 1.0122x over previous
#include <cuda_runtime.h>
#include <cuda_bf16.h>
#include <cuda_fp16.h>
#include <cstdint>

#define NN 100000
#define EE 1600000
#define DD 128
#define SCAN_CHUNK 1024
#define SCAN_B ((NN + SCAN_CHUNK - 1) / SCAN_CHUNK)   // 98

// ---------------- static device scratch (no allocations allowed) ----------------
__device__ int    g_outdeg[NN];
__device__ int    g_indeg[NN];
__device__ float  g_nsrc[NN];
__device__ float  g_ndst[NN];
__device__ int    g_off[NN + 1];
__device__ int    g_cur[NN];
__device__ int    g_part[SCAN_B + 1];
__device__ int    g_esrc[EE];
__device__ __half g_G[(size_t)NN * DD];    // ns-scaled GEMM output (gather source)
__device__ __half g_h1[(size_t)NN * DD];   // layer-1 activations
__device__ __half g_Whi1[DD * DD];         // W1 split (fp16 hi/lo, transposed)
__device__ __half g_Wlo1[DD * DD];
__device__ __half g_Whi2[DD * DD];         // W2 split (fp16 hi/lo, transposed)
__device__ __half g_Wlo2[DD * DD];

__device__ __forceinline__ uint32_t smem_u32(const void* p) {
    uint32_t a;
    asm("{ .reg .u64 t; cvta.to.shared.u64 t, %1; cvt.u32.u64 %0, t; }" : "=r"(a) : "l"(p));
    return a;
}

// ---------------- fused setup: zero degrees + split/transpose both W ----------------
__global__ __launch_bounds__(256)
void setup_kernel(const float* __restrict__ W1, const float* __restrict__ W2, int n) {
    int i = blockIdx.x * blockDim.x + threadIdx.x;
    if (i < n) { g_outdeg[i] = 0; g_indeg[i] = 0; }
    if (i < DD * DD) {
        int k = i >> 7, nn = i & 127;
        float w1 = W1[i];
        __half h1v = __float2half_rn(w1);
        g_Whi1[nn * DD + k] = h1v;
        g_Wlo1[nn * DD + k] = __float2half_rn(w1 - __half2float(h1v));
        float w2 = W2[i];
        __half h2 = __float2half_rn(w2);
        g_Whi2[nn * DD + k] = h2;
        g_Wlo2[nn * DD + k] = __float2half_rn(w2 - __half2float(h2));
    }
}

// 2 edges per thread
__global__ __launch_bounds__(256)
void count_deg_kernel(const int* __restrict__ src, const int* __restrict__ dst,
                      int E2, int E, int n) {
    int t = blockIdx.x * blockDim.x + threadIdx.x;
    if (t < E2) {
        int e = t * 2;
        if (e + 1 < E) {
            int2 s = *(const int2*)(src + e);
            int2 d = *(const int2*)(dst + e);
            if ((unsigned)s.x < (unsigned)n) atomicAdd(&g_outdeg[s.x], 1);
            if ((unsigned)s.y < (unsigned)n) atomicAdd(&g_outdeg[s.y], 1);
            if ((unsigned)d.x < (unsigned)n) atomicAdd(&g_indeg[d.x], 1);
            if ((unsigned)d.y < (unsigned)n) atomicAdd(&g_indeg[d.y], 1);
        } else {
            int s = src[e], d = dst[e];
            if ((unsigned)s < (unsigned)n) atomicAdd(&g_outdeg[s], 1);
            if ((unsigned)d < (unsigned)n) atomicAdd(&g_indeg[d], 1);
        }
    }
}

// ---- scan pass 1 (+ fused norm computation) ----
__global__ __launch_bounds__(256)
void scan_reduce_kernel(int n) {
    __shared__ int wsum[8];
    int b = blockIdx.x;
    int tid = threadIdx.x;
    int idx = b * SCAN_CHUNK + tid * 4;
    int s = 0;
    #pragma unroll
    for (int t = 0; t < 4; t++)
        if (idx + t < n) {
            int ind = g_indeg[idx + t];
            s += ind;
            g_ndst[idx + t] = rsqrtf(fmaxf((float)ind, 1.0f));
            g_nsrc[idx + t] = rsqrtf(fmaxf((float)g_outdeg[idx + t], 1.0f));
        }
    #pragma unroll
    for (int o = 16; o > 0; o >>= 1) s += __shfl_down_sync(0xffffffffu, s, o);
    int lane = tid & 31, wid = tid >> 5;
    if (lane == 0) wsum[wid] = s;
    __syncthreads();
    if (tid == 0) {
        int t = 0;
        #pragma unroll
        for (int w = 0; w < 8; w++) t += wsum[w];
        g_part[b] = t;
    }
}

__global__ __launch_bounds__(128)
void scan_partials_kernel(int B, int E) {
    __shared__ int sdata[128];
    int tid = threadIdx.x;
    int v = (tid < B) ? g_part[tid] : 0;
    sdata[tid] = v;
    __syncthreads();
    #pragma unroll
    for (int o = 1; o < 128; o <<= 1) {
        int t = (tid >= o) ? sdata[tid - o] : 0;
        __syncthreads();
        sdata[tid] += t;
        __syncthreads();
    }
    if (tid < B) g_part[tid] = sdata[tid] - v;
    if (tid == 0) g_off[NN] = E;
}

__global__ __launch_bounds__(256)
void scan_down_kernel(int n) {
    __shared__ int wscan[8];
    int b = blockIdx.x;
    int tid = threadIdx.x;
    int lane = tid & 31, wid = tid >> 5;
    int idx = b * SCAN_CHUNK + tid * 4;
    int v0 = 0, v1 = 0, v2 = 0, v3 = 0;
    if (idx + 0 < n) v0 = g_indeg[idx + 0];
    if (idx + 1 < n) v1 = g_indeg[idx + 1];
    if (idx + 2 < n) v2 = g_indeg[idx + 2];
    if (idx + 3 < n) v3 = g_indeg[idx + 3];
    int tsum = v0 + v1 + v2 + v3;
    int x = tsum;
    #pragma unroll
    for (int o = 1; o < 32; o <<= 1) {
        int y = __shfl_up_sync(0xffffffffu, x, o);
        if (lane >= o) x += y;
    }
    if (lane == 31) wscan[wid] = x;
    __syncthreads();
    if (wid == 0 && lane < 8) {
        int s = wscan[lane];
        #pragma unroll
        for (int o = 1; o < 8; o <<= 1) {
            int y = __shfl_up_sync(0x000000ffu, s, o);
            if (lane >= o) s += y;
        }
        wscan[lane] = s;
    }
    __syncthreads();
    int base = g_part[b] + (wid ? wscan[wid - 1] : 0) + (x - tsum);
    if (idx + 0 < n) { g_off[idx + 0] = base;            g_cur[idx + 0] = base; }
    if (idx + 1 < n) { g_off[idx + 1] = base + v0;       g_cur[idx + 1] = base + v0; }
    if (idx + 2 < n) { int t = base + v0 + v1;      g_off[idx + 2] = t; g_cur[idx + 2] = t; }
    if (idx + 3 < n) { int t = base + v0 + v1 + v2; g_off[idx + 3] = t; g_cur[idx + 3] = t; }
}

// 2 edges per thread
__global__ __launch_bounds__(256)
void fill_csr_kernel(const int* __restrict__ src, const int* __restrict__ dst,
                     int E2, int E, int n) {
    int t = blockIdx.x * blockDim.x + threadIdx.x;
    if (t < E2) {
        int e = t * 2;
        if (e + 1 < E) {
            int2 s = *(const int2*)(src + e);
            int2 d = *(const int2*)(dst + e);
            if ((unsigned)s.x < (unsigned)n && (unsigned)d.x < (unsigned)n)
                g_esrc[atomicAdd(&g_cur[d.x], 1)] = s.x;
            if ((unsigned)s.y < (unsigned)n && (unsigned)d.y < (unsigned)n)
                g_esrc[atomicAdd(&g_cur[d.y], 1)] = s.y;
        } else {
            int s = src[e], d = dst[e];
            if ((unsigned)s < (unsigned)n && (unsigned)d < (unsigned)n)
                g_esrc[atomicAdd(&g_cur[d], 1)] = s;
        }
    }
}

// ---------------- pull-based SpMM (fp16 gather) + fused nd/bias/relu ----------------
template <typename TOut>
__global__ __launch_bounds__(256)
void spmm_kernel(const __half* __restrict__ G, const float* __restrict__ bias,
                 TOut* __restrict__ out, int n) {
    int gw = (blockIdx.x * blockDim.x + threadIdx.x) >> 5;
    if (gw >= n) return;
    int lane = threadIdx.x & 31;
    int beg = g_off[gw];
    int end = g_off[gw + 1];
    const uint2* hp = (const uint2*)G;
    float4 acc = make_float4(0.f, 0.f, 0.f, 0.f);
    int e = beg;
    for (; e + 3 < end; e += 4) {
        int u0 = g_esrc[e], u1 = g_esrc[e + 1], u2 = g_esrc[e + 2], u3 = g_esrc[e + 3];
        uint2 a = hp[(size_t)u0 * 32 + lane];
        uint2 b = hp[(size_t)u1 * 32 + lane];
        uint2 c = hp[(size_t)u2 * 32 + lane];
        uint2 d = hp[(size_t)u3 * 32 + lane];
        float2 f;
        f = __half22float2(*(__half2*)&a.x); acc.x += f.x; acc.y += f.y;
        f = __half22float2(*(__half2*)&a.y); acc.z += f.x; acc.w += f.y;
        f = __half22float2(*(__half2*)&b.x); acc.x += f.x; acc.y += f.y;
        f = __half22float2(*(__half2*)&b.y); acc.z += f.x; acc.w += f.y;
        f = __half22float2(*(__half2*)&c.x); acc.x += f.x; acc.y += f.y;
        f = __half22float2(*(__half2*)&c.y); acc.z += f.x; acc.w += f.y;
        f = __half22float2(*(__half2*)&d.x); acc.x += f.x; acc.y += f.y;
        f = __half22float2(*(__half2*)&d.y); acc.z += f.x; acc.w += f.y;
    }
    for (; e < end; e++) {
        uint2 a = hp[(size_t)g_esrc[e] * 32 + lane];
        float2 f;
        f = __half22float2(*(__half2*)&a.x); acc.x += f.x; acc.y += f.y;
        f = __half22float2(*(__half2*)&a.y); acc.z += f.x; acc.w += f.y;
    }
    float nd = g_ndst[gw];
    float4 b4 = ((const float4*)bias)[lane];
    float4 o;
    o.x = fmaxf(acc.x * nd + b4.x, 0.f);
    o.y = fmaxf(acc.y * nd + b4.y, 0.f);
    o.z = fmaxf(acc.z * nd + b4.z, 0.f);
    o.w = fmaxf(acc.w * nd + b4.w, 0.f);
    if constexpr (sizeof(TOut) == 4) {
        ((float4*)out)[(size_t)gw * 32 + lane] = o;
    } else {
        uint2 p;
        *(__half2*)&p.x = __floats2half2_rn(o.x, o.y);
        *(__half2*)&p.y = __floats2half2_rn(o.z, o.w);
        ((uint2*)out)[(size_t)gw * 32 + lane] = p;
    }
}

// ---------------- HMMA GEMM: C = ns ⊙ (A @ W), fp16 out ----------------
// 2x4 warp tiling: warp = 64 M-rows x 32 N-cols. W frags reused across 4 A-blocks in regs.
// A single fp16 smem tile; W fp16 hi/lo 2-pass. smem 104.4KB -> 2 CTAs/SM.
#define GP 272
#define TROWS 128
#define SM_A   0
#define SM_WHI (TROWS * GP)
#define SM_WLO (SM_WHI + 128 * GP)
#define GEMM_SMEM ((TROWS + 2 * 128) * GP)   // 104448

__device__ __forceinline__ void ldsm_x4(uint32_t* r, uint32_t addr) {
    asm volatile("ldmatrix.sync.aligned.m8n8.x4.shared.b16 {%0,%1,%2,%3}, [%4];"
                 : "=r"(r[0]), "=r"(r[1]), "=r"(r[2]), "=r"(r[3]) : "r"(addr));
}
__device__ __forceinline__ void mma_f16(float* c, const uint32_t* a, uint32_t b0, uint32_t b1) {
    asm volatile("mma.sync.aligned.m16n8k16.row.col.f32.f16.f16.f32 "
                 "{%0,%1,%2,%3}, {%4,%5,%6,%7}, {%8,%9}, {%0,%1,%2,%3};"
                 : "+f"(c[0]), "+f"(c[1]), "+f"(c[2]), "+f"(c[3])
                 : "r"(a[0]), "r"(a[1]), "r"(a[2]), "r"(a[3]), "r"(b0), "r"(b1));
}

template <int AFP32>
__global__ __launch_bounds__(256, 2)
void gemm_tc_kernel(const void* __restrict__ Av,
                    const __half* __restrict__ Whi,
                    const __half* __restrict__ Wlo,
                    __half* __restrict__ C, int n) {
    extern __shared__ char sm[];
    uint32_t base = smem_u32(sm);
    const int tid = threadIdx.x;
    const int w = tid >> 5, lane = tid & 31;
    const int wm = w >> 2;           // 0..1 : M-warp  (64 rows)
    const int wn = w & 3;            // 0..3 : N-warp  (32 cols)
    const int row0 = blockIdx.x * TROWS;

    // W tiles: 128 rows x 256B
    for (int i = tid; i < 2048; i += 256) {
        int rr = i >> 4, q = i & 15;
        *(uint4*)(sm + SM_WHI + rr * GP + q * 16) = ((const uint4*)Whi)[rr * 16 + q];
        *(uint4*)(sm + SM_WLO + rr * GP + q * 16) = ((const uint4*)Wlo)[rr * 16 + q];
    }
    // A tile (fp16), 2 threads per row x 64 cols
    {
        int r = tid >> 1, half_sel = tid & 1;
        int gr = row0 + r;
        if constexpr (AFP32) {
            const float4* ap = (const float4*)((const float*)Av + (size_t)gr * DD + half_sel * 64);
            #pragma unroll
            for (int i = 0; i < 16; i += 2) {
                float4 v0 = make_float4(0.f, 0.f, 0.f, 0.f);
                float4 v1 = make_float4(0.f, 0.f, 0.f, 0.f);
                if (gr < n) { v0 = ap[i]; v1 = ap[i + 1]; }
                uint4 pk;
                *(__half2*)&pk.x = __floats2half2_rn(v0.x, v0.y);
                *(__half2*)&pk.y = __floats2half2_rn(v0.z, v0.w);
                *(__half2*)&pk.z = __floats2half2_rn(v1.x, v1.y);
                *(__half2*)&pk.w = __floats2half2_rn(v1.z, v1.w);
                *(uint4*)(sm + SM_A + r * GP + half_sel * 128 + i * 8) = pk;
            }
        } else {
            const uint4* ap = (const uint4*)((const __half*)Av + (size_t)gr * DD + half_sel * 64);
            #pragma unroll
            for (int i = 0; i < 8; i++) {
                uint4 v = make_uint4(0u, 0u, 0u, 0u);
                if (gr < n) v = ap[i];
                *(uint4*)(sm + SM_A + r * GP + half_sel * 128 + i * 16) = v;
            }
        }
    }
    __syncthreads();

    // acc[ab][np][4]: 4 A-blocks (16 rows) x 4 n8-blocks (8 cols)
    float acc[4][4][4];
    #pragma unroll
    for (int a = 0; a < 4; a++)
        #pragma unroll
        for (int p = 0; p < 4; p++)
            #pragma unroll
            for (int q = 0; q < 4; q++) acc[a][p][q] = 0.f;

    // A lane addressing (ldsm x4 = 16 rows x k16)
    int i4 = lane >> 3, l7 = lane & 7;
    uint32_t aRowIn = (uint32_t)((i4 & 1) * 8 + l7);
    uint32_t aK8    = (uint32_t)((i4 >> 1) * 8);
    uint32_t aBase = base + SM_A + (wm * 64 + aRowIn) * GP + aK8 * 2;
    // W lane addressing (ldsm x4 = 16 N-rows x k16)
    uint32_t wRowIn = (uint32_t)((lane & 7) + ((lane >> 4) << 3));
    uint32_t wK8    = (uint32_t)(((lane >> 3) & 1) * 8);
    uint32_t wHi = base + SM_WHI + (wn * 32 + wRowIn) * GP + wK8 * 2;
    uint32_t wLo = base + SM_WLO + (wn * 32 + wRowIn) * GP + wK8 * 2;

    #pragma unroll
    for (int kk = 0; kk < 8; kk++) {
        uint32_t wh0[4], wh1[4], wl0[4], wl1[4];
        ldsm_x4(wh0, wHi + kk * 32);               // j-pair 0: n8 blocks 0,1
        ldsm_x4(wh1, wHi + 16 * GP + kk * 32);     // j-pair 1: n8 blocks 2,3
        ldsm_x4(wl0, wLo + kk * 32);
        ldsm_x4(wl1, wLo + 16 * GP + kk * 32);
        #pragma unroll
        for (int ab = 0; ab < 4; ab++) {
            uint32_t ah[4];
            ldsm_x4(ah, aBase + ab * 16 * GP + kk * 32);
            mma_f16(acc[ab][0], ah, wh0[0], wh0[1]);
            mma_f16(acc[ab][1], ah, wh0[2], wh0[3]);
            mma_f16(acc[ab][2], ah, wh1[0], wh1[1]);
            mma_f16(acc[ab][3], ah, wh1[2], wh1[3]);
            mma_f16(acc[ab][0], ah, wl0[0], wl0[1]);
            mma_f16(acc[ab][1], ah, wl0[2], wl0[3]);
            mma_f16(acc[ab][2], ah, wl1[0], wl1[1]);
            mma_f16(acc[ab][3], ah, wl1[2], wl1[3]);
        }
    }

    // epilogue: scale rows by ns, write fp16. warp owns rows wm*64.. (+64), cols wn*32.. (+32)
    int c0 = (lane & 3) * 2;
    #pragma unroll
    for (int ab = 0; ab < 4; ab++) {
        int r0 = row0 + wm * 64 + ab * 16 + (lane >> 2);
        float ns0 = (r0 < n) ? g_nsrc[r0] : 0.f;
        float ns1 = (r0 + 8 < n) ? g_nsrc[r0 + 8] : 0.f;
        #pragma unroll
        for (int np = 0; np < 4; np++) {
            int nn = wn * 32 + np * 8 + c0;
            if (r0 < n)
                *(__half2*)(C + (size_t)r0 * DD + nn) = __floats2half2_rn(acc[ab][np][0] * ns0, acc[ab][np][1] * ns0);
            if (r0 + 8 < n)
                *(__half2*)(C + (size_t)(r0 + 8) * DD + nn) = __floats2half2_rn(acc[ab][np][2] * ns1, acc[ab][np][3] * ns1);
        }
    }
}

// ---------------- launch ----------------
extern "C" void kernel_launch(void* const* d_in, const int* in_sizes, int n_in,
                              void* d_out, int out_size) {
    const float* features = (const float*)d_in[0];
    const int*   src      = (const int*)d_in[1];   // jnp.int64 downgrades to int32 (x64 off)
    const int*   dst      = (const int*)d_in[2];
    const float* W1       = (const float*)d_in[3];
    const float* b1       = (const float*)d_in[4];
    const float* W2       = (const float*)d_in[5];
    const float* b2       = (const float*)d_in[6];
    float*       out      = (float*)d_out;

    int n = in_sizes[0] / DD;   // 100000
    int E = in_sizes[1];        // 1600000

    __half *G, *h1, *whi1, *wlo1, *whi2, *wlo2;
    cudaGetSymbolAddress((void**)&G, g_G);
    cudaGetSymbolAddress((void**)&h1, g_h1);
    cudaGetSymbolAddress((void**)&whi1, g_Whi1);
    cudaGetSymbolAddress((void**)&wlo1, g_Wlo1);
    cudaGetSymbolAddress((void**)&whi2, g_Whi2);
    cudaGetSymbolAddress((void**)&wlo2, g_Wlo2);

    cudaFuncSetAttribute(gemm_tc_kernel<1>,
                         cudaFuncAttributeMaxDynamicSharedMemorySize, GEMM_SMEM);
    cudaFuncSetAttribute(gemm_tc_kernel<0>,
                         cudaFuncAttributeMaxDynamicSharedMemorySize, GEMM_SMEM);

    int tb = 256;
    int gN = (n + tb - 1) / tb;
    int E2 = (E + 1) / 2;
    int gE2 = (E2 + tb - 1) / tb;
    int gSp = ((n * 32) + tb - 1) / tb;
    int gGemm = (n + TROWS - 1) / TROWS;
    int B = (n + SCAN_CHUNK - 1) / SCAN_CHUNK;

    setup_kernel<<<gN, tb>>>(W1, W2, n);
    count_deg_kernel<<<gE2, tb>>>(src, dst, E2, E, n);
    scan_reduce_kernel<<<B, 256>>>(n);
    gemm_tc_kernel<1><<<gGemm, 256, GEMM_SMEM>>>(features, whi1, wlo1, G, n);
    scan_partials_kernel<<<1, 128>>>(B, E);
    scan_down_kernel<<<B, 256>>>(n);
    fill_csr_kernel<<<gE2, tb>>>(src, dst, E2, E, n);

    spmm_kernel<__half><<<gSp, tb>>>(G, b1, h1, n);
    gemm_tc_kernel<0><<<gGemm, 256, GEMM_SMEM>>>(h1, whi2, wlo2, G, n);
    spmm_kernel<float><<<gSp, tb>>>(G, b2, out, n);
}